// round 5
// baseline (speedup 1.0000x reference)
#include <cuda_runtime.h>
#include <cuda_bf16.h>
#include <math.h>
#include <stdint.h>

// ---------------- problem dims ----------------
#define BB 2
#define LL 4096
#define DD 1024
#define NN 16
#define KK 4
#define SEG 32
#define TSEG 128            // LL/SEG
#define MROWS (BB*LL)       // 8192
#define Y_ELEMS (BB*LL*DD)  // 8388608

// ---------------- scratch ----------------
__device__ float g_xssm[Y_ELEMS];
__device__ float g_gate[Y_ELEMS];    // silu(gate)
__device__ float g_xconv[Y_ELEMS];
__device__ float g_yg[Y_ELEMS];      // y*silu(gate), tf32-rounded
__device__ float g_B[BB*LL*NN];
__device__ float g_C[BB*LL*NN];
__device__ float g_xr[Y_ELEMS];      // tf32-rounded x
__device__ float g_wr[2*DD*DD];      // tf32-rounded W_in
__device__ float g_wor[DD*DD];       // tf32-rounded W_out
__device__ float g_hseg[BB*SEG*NN*DD];
__device__ float g_h0[BB*SEG*NN*DD];

__device__ __forceinline__ float rtf(float f) {
    uint32_t r; asm("cvt.rna.tf32.f32 %0, %1;" : "=r"(r) : "f"(f));
    return __uint_as_float(r);
}

// ---------------- tf32 pre-round ----------------
__global__ void round_tf32_kernel(const float* __restrict__ src,
                                  float* __restrict__ dst, int n4)
{
    int i = blockIdx.x * blockDim.x + threadIdx.x;
    if (i >= n4) return;
    float4 v = ((const float4*)src)[i];
    v.x = rtf(v.x); v.y = rtf(v.y); v.z = rtf(v.z); v.w = rtf(v.w);
    ((float4*)dst)[i] = v;
}

// =================== tf32 mma.sync GEMM, 128x256 block, 64x64 warp ======
#define GBM 128
#define GBN 256
#define GBK 16
#define ASTRIDE (GBK+4)             // 20
#define BSTRIDE (GBN+8)             // 264
#define A_STG (GBM*ASTRIDE)         // 2560 floats
#define B_STG (GBK*BSTRIDE)         // 4224 floats
#define STAGES 3
#define GEMM_SMEM (STAGES*(A_STG+B_STG)*4)   // 81408 bytes

__device__ __forceinline__ void cpasync16(void* dst, const void* src) {
    uint32_t s = (uint32_t)__cvta_generic_to_shared(dst);
    asm volatile("cp.async.cg.shared.global [%0], [%1], 16;\n" :: "r"(s), "l"(src));
}

__global__ __launch_bounds__(256, 1)
void tc_gemm_kernel(const float* __restrict__ A, const float* __restrict__ Bm,
                    const float* __restrict__ bias,
                    float* __restrict__ C0, float* __restrict__ C1,
                    int M, int N, int K, int mode)
{
    extern __shared__ float sm[];
    float* As_ = sm;                    // [STAGES][GBM][ASTRIDE]
    float* Bs_ = sm + STAGES * A_STG;   // [STAGES][GBK][BSTRIDE]

    const int tid  = threadIdx.x;
    const int lane = tid & 31;
    const int wid  = tid >> 5;
    const int wm   = wid >> 2;          // 0..1 -> m offset wm*64
    const int wn   = wid & 3;           // 0..3 -> n offset wn*64
    const int row_c = blockIdx.y * GBM;
    const int col_c = blockIdx.x * GBN;
    const int r  = lane >> 2;           // 0..7
    const int cq = lane & 3;            // 0..3

    float acc[4][8][4];
    #pragma unroll
    for (int i = 0; i < 4; i++)
        #pragma unroll
        for (int j = 0; j < 8; j++)
            #pragma unroll
            for (int v = 0; v < 4; v++) acc[i][j][v] = 0.0f;

    // A: 128x16 = 512 float4 (2/thread); B: 16x256 = 1024 float4 (4/thread)
    const int a_row0 = tid >> 2;            // 0..63 (+64)
    const int a_col0 = (tid & 3) * 4;
    const int b_row0 = tid >> 6;            // 0..3 (+4,+8,+12)
    const int b_col0 = (tid & 63) * 4;

    auto prefetch = [&](int k0, int st) {
        float* Asb = As_ + st * A_STG;
        float* Bsb = Bs_ + st * B_STG;
        #pragma unroll
        for (int s = 0; s < 2; s++) {
            int ar = a_row0 + s * 64;
            cpasync16(&Asb[ar * ASTRIDE + a_col0],
                      A + (size_t)(row_c + ar) * K + k0 + a_col0);
        }
        #pragma unroll
        for (int s = 0; s < 4; s++) {
            int br = b_row0 + s * 4;
            cpasync16(&Bsb[br * BSTRIDE + b_col0],
                      Bm + (size_t)(k0 + br) * N + col_c + b_col0);
        }
        asm volatile("cp.async.commit_group;");
    };

    const int nchunks = K / GBK;   // 64
    prefetch(0, 0);
    prefetch(GBK, 1);

    for (int ch = 0; ch < nchunks; ch++) {
        if (ch >= nchunks - 2) asm volatile("cp.async.wait_group 0;");
        else                   asm volatile("cp.async.wait_group 1;");
        __syncthreads();
        if (ch + 2 < nchunks) prefetch((ch + 2) * GBK, (ch + 2) % STAGES);

        const float* Asb = As_ + (ch % STAGES) * A_STG;
        const float* Bsb = Bs_ + (ch % STAGES) * B_STG;

        #pragma unroll
        for (int ks = 0; ks < GBK / 8; ks++) {
            uint32_t af[4][4], bf[8][2];
            #pragma unroll
            for (int mi = 0; mi < 4; mi++) {
                int row = wm * 64 + mi * 16 + r;
                int c   = ks * 8 + cq;
                af[mi][0] = __float_as_uint(Asb[row * ASTRIDE + c]);
                af[mi][1] = __float_as_uint(Asb[(row + 8) * ASTRIDE + c]);
                af[mi][2] = __float_as_uint(Asb[row * ASTRIDE + c + 4]);
                af[mi][3] = __float_as_uint(Asb[(row + 8) * ASTRIDE + c + 4]);
            }
            #pragma unroll
            for (int ni = 0; ni < 8; ni++) {
                int col = wn * 64 + ni * 8 + r;
                int kr  = ks * 8 + cq;
                bf[ni][0] = __float_as_uint(Bsb[kr * BSTRIDE + col]);
                bf[ni][1] = __float_as_uint(Bsb[(kr + 4) * BSTRIDE + col]);
            }
            #pragma unroll
            for (int mi = 0; mi < 4; mi++)
                #pragma unroll
                for (int ni = 0; ni < 8; ni++) {
                    asm volatile(
                        "mma.sync.aligned.m16n8k8.row.col.f32.tf32.tf32.f32 "
                        "{%0,%1,%2,%3}, {%4,%5,%6,%7}, {%8,%9}, {%0,%1,%2,%3};"
                        : "+f"(acc[mi][ni][0]), "+f"(acc[mi][ni][1]),
                          "+f"(acc[mi][ni][2]), "+f"(acc[mi][ni][3])
                        : "r"(af[mi][0]), "r"(af[mi][1]),
                          "r"(af[mi][2]), "r"(af[mi][3]),
                          "r"(bf[ni][0]), "r"(bf[ni][1]));
                }
        }
        __syncthreads();
    }

    // epilogue (float2 stores; each 256-wide block entirely in one half)
    const int halfN = N >> 1;
    const bool gate_side = (mode == 1) && (col_c >= halfN);
    const bool split = (mode == 1);
    float* dst = gate_side ? C1 : C0;
    const int outw = split ? halfN : N;
    const int colsub = gate_side ? halfN : 0;

    #pragma unroll
    for (int mi = 0; mi < 4; mi++) {
        #pragma unroll
        for (int ni = 0; ni < 8; ni++) {
            int r0   = row_c + wm * 64 + mi * 16 + r;
            int colg = col_c + wn * 64 + ni * 8 + cq * 2;
            float b0 = bias[colg], b1 = bias[colg + 1];
            #pragma unroll
            for (int hv = 0; hv < 2; hv++) {
                int rr = r0 + hv * 8;
                float2 v;
                v.x = acc[mi][ni][hv * 2 + 0] + b0;
                v.y = acc[mi][ni][hv * 2 + 1] + b1;
                if (gate_side) {
                    v.x = v.x / (1.0f + expf(-v.x));
                    v.y = v.y / (1.0f + expf(-v.y));
                }
                *(float2*)(dst + (size_t)rr * outw + colg - colsub) = v;
            }
        }
    }
}

// ---------------- depthwise causal conv (K=4) + SiLU ----------------
__global__ void conv_silu_kernel(const float* __restrict__ w,
                                 const float* __restrict__ cb)
{
    int idx = blockIdx.x * blockDim.x + threadIdx.x;
    if (idx >= Y_ELEMS / 4) return;
    int d  = idx & (DD - 1);
    int lq = (idx >> 10) & (LL / 4 - 1);
    int b  = idx >> 20;
    int l0 = lq * 4;
    const float* base = g_xssm + (size_t)b * LL * DD + d;
    float w0 = w[d * KK + 0], w1 = w[d * KK + 1],
          w2 = w[d * KK + 2], w3 = w[d * KK + 3];
    float bias = cb[d];
    float xm3 = (l0 >= 3) ? base[(size_t)(l0 - 3) * DD] : 0.0f;
    float xm2 = (l0 >= 2) ? base[(size_t)(l0 - 2) * DD] : 0.0f;
    float xm1 = (l0 >= 1) ? base[(size_t)(l0 - 1) * DD] : 0.0f;
    float x0 = base[(size_t)(l0 + 0) * DD];
    float x1 = base[(size_t)(l0 + 1) * DD];
    float x2 = base[(size_t)(l0 + 2) * DD];
    float x3 = base[(size_t)(l0 + 3) * DD];
    float* outp = g_xconv + (size_t)b * LL * DD + d;
    float v;
    v = bias + w0*xm3 + w1*xm2 + w2*xm1 + w3*x0;
    outp[(size_t)(l0+0)*DD] = v / (1.0f + expf(-v));
    v = bias + w0*xm2 + w1*xm1 + w2*x0 + w3*x1;
    outp[(size_t)(l0+1)*DD] = v / (1.0f + expf(-v));
    v = bias + w0*xm1 + w1*x0 + w2*x1 + w3*x2;
    outp[(size_t)(l0+2)*DD] = v / (1.0f + expf(-v));
    v = bias + w0*x0 + w1*x1 + w2*x2 + w3*x3;
    outp[(size_t)(l0+3)*DD] = v / (1.0f + expf(-v));
}

// ---------------- BC = x_conv @ W_x + b_x (W staged in smem once) --------
#define BC_SMEM (DD*32*4 + 8*DD*4 + 8*8*32*4)

__global__ __launch_bounds__(256)
void bc_kernel(const float* __restrict__ Wx, const float* __restrict__ bx)
{
    extern __shared__ float sm[];
    float* Wsm  = sm;
    float* rows = sm + DD * 32;
    float* psum = rows + 8 * DD;

    const int tid = threadIdx.x;
    const int c   = tid & 31;
    const int ks  = tid >> 5;
    const int r0  = blockIdx.x * 64;

    for (int i = tid; i < DD * 32 / 4; i += 256)
        ((float4*)Wsm)[i] = ((const float4*)Wx)[i];
    __syncthreads();

    for (int g = 0; g < 8; g++) {
        const float* src = g_xconv + (size_t)(r0 + g * 8) * DD;
        for (int i = tid; i < 8 * DD / 4; i += 256)
            ((float4*)rows)[i] = ((const float4*)src)[i];
        __syncthreads();

        float acc[8];
        #pragma unroll
        for (int rr = 0; rr < 8; rr++) acc[rr] = 0.0f;

        const int kbase = ks * 128;
        for (int k4 = 0; k4 < 128; k4 += 4) {
            int k = kbase + k4;
            float w0 = Wsm[(k + 0) * 32 + c];
            float w1 = Wsm[(k + 1) * 32 + c];
            float w2 = Wsm[(k + 2) * 32 + c];
            float w3 = Wsm[(k + 3) * 32 + c];
            #pragma unroll
            for (int rr = 0; rr < 8; rr++) {
                float4 xv = *(const float4*)&rows[rr * DD + k];
                acc[rr] = fmaf(xv.x, w0, fmaf(xv.y, w1,
                          fmaf(xv.z, w2, fmaf(xv.w, w3, acc[rr]))));
            }
        }
        #pragma unroll
        for (int rr = 0; rr < 8; rr++)
            psum[(rr * 8 + ks) * 32 + c] = acc[rr];
        __syncthreads();

        {
            int rr = tid >> 5;
            int c2 = tid & 31;
            float s = bx[c2];
            #pragma unroll
            for (int q = 0; q < 8; q++) s += psum[(rr * 8 + q) * 32 + c2];
            int r = r0 + g * 8 + rr;
            if (c2 < NN) g_B[r * NN + c2] = s;
            else         g_C[r * NN + (c2 - NN)] = s;
        }
        __syncthreads();
    }
}

// ---------------- scan pass 1 ----------------
__global__ __launch_bounds__(256)
void scan1_kernel(const float* __restrict__ A_log)
{
    __shared__ float Xsm[32][256];
    __shared__ __align__(16) float Bsm[32][16];

    const int tid = threadIdx.x;
    const int dt  = blockIdx.x & 3;
    const int s   = (blockIdx.x >> 2) & 31;
    const int b   = blockIdx.x >> 7;
    const int d   = dt * 256 + tid;

    float Adn[16];
    #pragma unroll
    for (int n = 0; n < 16; n++) Adn[n] = expf(-expf(A_log[d * NN + n]));

    float h[16];
    #pragma unroll
    for (int n = 0; n < 16; n++) h[n] = 0.0f;

    const float* xcp = g_xconv + (size_t)b * LL * DD + dt * 256;
    const float* Bp  = g_B + (size_t)b * LL * NN;
    const int t0 = s * TSEG;

    for (int cc = 0; cc < 4; cc++) {
        int tb = t0 + cc * 32;
        if (tid < 128)
            ((float4*)Bsm)[tid] = ((const float4*)(Bp + (size_t)tb * NN))[tid];
        #pragma unroll 8
        for (int i = 0; i < 32; i++)
            Xsm[i][tid] = xcp[(size_t)(tb + i) * DD + tid];
        __syncthreads();
        #pragma unroll 4
        for (int tl = 0; tl < 32; tl++) {
            float xc = Xsm[tl][tid];
            float4 b0 = *(const float4*)&Bsm[tl][0];
            float4 b1 = *(const float4*)&Bsm[tl][4];
            float4 b2 = *(const float4*)&Bsm[tl][8];
            float4 b3 = *(const float4*)&Bsm[tl][12];
            h[0]  = fmaf(Adn[0],  h[0],  xc * b0.x);
            h[1]  = fmaf(Adn[1],  h[1],  xc * b0.y);
            h[2]  = fmaf(Adn[2],  h[2],  xc * b0.z);
            h[3]  = fmaf(Adn[3],  h[3],  xc * b0.w);
            h[4]  = fmaf(Adn[4],  h[4],  xc * b1.x);
            h[5]  = fmaf(Adn[5],  h[5],  xc * b1.y);
            h[6]  = fmaf(Adn[6],  h[6],  xc * b1.z);
            h[7]  = fmaf(Adn[7],  h[7],  xc * b1.w);
            h[8]  = fmaf(Adn[8],  h[8],  xc * b2.x);
            h[9]  = fmaf(Adn[9],  h[9],  xc * b2.y);
            h[10] = fmaf(Adn[10], h[10], xc * b2.z);
            h[11] = fmaf(Adn[11], h[11], xc * b2.w);
            h[12] = fmaf(Adn[12], h[12], xc * b3.x);
            h[13] = fmaf(Adn[13], h[13], xc * b3.y);
            h[14] = fmaf(Adn[14], h[14], xc * b3.z);
            h[15] = fmaf(Adn[15], h[15], xc * b3.w);
        }
        __syncthreads();
    }
    #pragma unroll
    for (int n = 0; n < 16; n++)
        g_hseg[((size_t)(b * SEG + s) * NN + n) * DD + d] = h[n];
}

// ---------------- combine ----------------
__global__ __launch_bounds__(256)
void combine_kernel(const float* __restrict__ A_log, float* __restrict__ fstate)
{
    int idx = blockIdx.x * 256 + threadIdx.x;
    int d = idx & (DD - 1);
    int bn = idx >> 10;
    int n = bn & 15;
    int b = bn >> 4;

    float Adn = expf(-expf(A_log[d * NN + n]));
    float p = Adn;
    #pragma unroll
    for (int i = 0; i < 7; i++) p = p * p;

    size_t base = ((size_t)(b * SEG) * NN + n) * DD + d;
    const size_t stride = (size_t)NN * DD;
    float h = 0.0f;
    #pragma unroll 4
    for (int s = 0; s < SEG; s++) {
        g_h0[base + s * stride] = h;
        h = fmaf(p, h, g_hseg[base + s * stride]);
    }
    #pragma unroll
    for (int off = 16; off >= 1; off >>= 1)
        h += __shfl_xor_sync(0xffffffffu, h, off);
    if ((threadIdx.x & 31) == 0)
        atomicAdd(&fstate[b * NN + n], h * (1.0f / (float)DD));
}

// ---------------- scan pass 2 ----------------
__global__ __launch_bounds__(256)
void scan2_kernel(const float* __restrict__ A_log, const float* __restrict__ Dp)
{
    __shared__ float Xsm[32][256];
    __shared__ __align__(16) float Bsm[32][16];
    __shared__ __align__(16) float Csm[32][16];

    const int tid = threadIdx.x;
    const int dt  = blockIdx.x & 3;
    const int s   = (blockIdx.x >> 2) & 31;
    const int b   = blockIdx.x >> 7;
    const int d   = dt * 256 + tid;

    float Adn[16];
    #pragma unroll
    for (int n = 0; n < 16; n++) Adn[n] = expf(-expf(A_log[d * NN + n]));
    const float Dd = Dp[d];

    float h[16];
    {
        size_t base = ((size_t)(b * SEG + s) * NN) * DD + d;
        #pragma unroll
        for (int n = 0; n < 16; n++) h[n] = g_h0[base + (size_t)n * DD];
    }

    const float* xcp = g_xconv + (size_t)b * LL * DD + dt * 256;
    const float* gp  = g_gate  + (size_t)b * LL * DD + dt * 256;
    float*       yp  = g_yg    + (size_t)b * LL * DD + dt * 256;
    const float* Bp  = g_B + (size_t)b * LL * NN;
    const float* Cp  = g_C + (size_t)b * LL * NN;
    const int t0 = s * TSEG;

    for (int cc = 0; cc < 4; cc++) {
        int tb = t0 + cc * 32;
        if (tid < 128) {
            ((float4*)Bsm)[tid] = ((const float4*)(Bp + (size_t)tb * NN))[tid];
            ((float4*)Csm)[tid] = ((const float4*)(Cp + (size_t)tb * NN))[tid];
        }
        #pragma unroll 8
        for (int i = 0; i < 32; i++)
            Xsm[i][tid] = xcp[(size_t)(tb + i) * DD + tid];
        __syncthreads();
        #pragma unroll 2
        for (int tl = 0; tl < 32; tl++) {
            float xc = Xsm[tl][tid];
            float4 b0 = *(const float4*)&Bsm[tl][0];
            float4 b1 = *(const float4*)&Bsm[tl][4];
            float4 b2 = *(const float4*)&Bsm[tl][8];
            float4 b3 = *(const float4*)&Bsm[tl][12];
            h[0]  = fmaf(Adn[0],  h[0],  xc * b0.x);
            h[1]  = fmaf(Adn[1],  h[1],  xc * b0.y);
            h[2]  = fmaf(Adn[2],  h[2],  xc * b0.z);
            h[3]  = fmaf(Adn[3],  h[3],  xc * b0.w);
            h[4]  = fmaf(Adn[4],  h[4],  xc * b1.x);
            h[5]  = fmaf(Adn[5],  h[5],  xc * b1.y);
            h[6]  = fmaf(Adn[6],  h[6],  xc * b1.z);
            h[7]  = fmaf(Adn[7],  h[7],  xc * b1.w);
            h[8]  = fmaf(Adn[8],  h[8],  xc * b2.x);
            h[9]  = fmaf(Adn[9],  h[9],  xc * b2.y);
            h[10] = fmaf(Adn[10], h[10], xc * b2.z);
            h[11] = fmaf(Adn[11], h[11], xc * b2.w);
            h[12] = fmaf(Adn[12], h[12], xc * b3.x);
            h[13] = fmaf(Adn[13], h[13], xc * b3.y);
            h[14] = fmaf(Adn[14], h[14], xc * b3.z);
            h[15] = fmaf(Adn[15], h[15], xc * b3.w);
            float4 c0 = *(const float4*)&Csm[tl][0];
            float4 c1 = *(const float4*)&Csm[tl][4];
            float4 c2 = *(const float4*)&Csm[tl][8];
            float4 c3 = *(const float4*)&Csm[tl][12];
            float y0 = fmaf(c0.x, h[0],  fmaf(c0.y, h[1],
                       fmaf(c0.z, h[2],  c0.w * h[3])));
            float y1 = fmaf(c1.x, h[4],  fmaf(c1.y, h[5],
                       fmaf(c1.z, h[6],  c1.w * h[7])));
            float y2 = fmaf(c2.x, h[8],  fmaf(c2.y, h[9],
                       fmaf(c2.z, h[10], c2.w * h[11])));
            float y3 = fmaf(c3.x, h[12], fmaf(c3.y, h[13],
                       fmaf(c3.z, h[14], c3.w * h[15])));
            float y = ((y0 + y1) + (y2 + y3)) + Dd * xc;
            float gv = gp[(size_t)(tb + tl) * DD + tid];
            yp[(size_t)(tb + tl) * DD + tid] = rtf(y * gv);
        }
        __syncthreads();
    }
}

__global__ void zero_tail_kernel(float* p)
{
    if (threadIdx.x < BB * NN) p[threadIdx.x] = 0.0f;
}

// ---------------- launcher ----------------
extern "C" void kernel_launch(void* const* d_in, const int* in_sizes, int n_in,
                              void* d_out, int out_size)
{
    const float* x      = (const float*)d_in[0];
    const float* W_in   = (const float*)d_in[1];
    const float* b_in   = (const float*)d_in[2];
    const float* conv_w = (const float*)d_in[3];
    const float* conv_b = (const float*)d_in[4];
    const float* W_x    = (const float*)d_in[5];
    const float* b_x    = (const float*)d_in[6];
    const float* A_log  = (const float*)d_in[7];
    const float* D_par  = (const float*)d_in[8];
    const float* W_out  = (const float*)d_in[9];
    const float* b_out  = (const float*)d_in[10];
    float* out = (float*)d_out;

    static int attr_done = 0;
    if (!attr_done) {
        cudaFuncSetAttribute(tc_gemm_kernel,
            cudaFuncAttributeMaxDynamicSharedMemorySize, GEMM_SMEM);
        cudaFuncSetAttribute(bc_kernel,
            cudaFuncAttributeMaxDynamicSharedMemorySize, BC_SMEM);
        attr_done = 1;
    }

    void *p_xssm, *p_gate, *p_yg, *p_xr, *p_wr, *p_wor;
    cudaGetSymbolAddress(&p_xssm, g_xssm);
    cudaGetSymbolAddress(&p_gate, g_gate);
    cudaGetSymbolAddress(&p_yg,   g_yg);
    cudaGetSymbolAddress(&p_xr,   g_xr);
    cudaGetSymbolAddress(&p_wr,   g_wr);
    cudaGetSymbolAddress(&p_wor,  g_wor);

    // 0) zero final_state tail
    zero_tail_kernel<<<1, 32>>>(out + Y_ELEMS);

    // 1) pre-round GEMM operands to tf32
    round_tf32_kernel<<<Y_ELEMS/4/256, 256>>>(x, (float*)p_xr, Y_ELEMS/4);
    round_tf32_kernel<<<(DD*2*DD)/4/256, 256>>>(W_in, (float*)p_wr, DD*2*DD/4);
    round_tf32_kernel<<<(DD*DD)/4/256, 256>>>(W_out, (float*)p_wor, DD*DD/4);

    // 2) GEMM1: [8192,1024]@[1024,2048] -> (x_ssm raw, silu(gate))
    {
        dim3 grid(2 * DD / GBN, MROWS / GBM);   // (8, 64)
        tc_gemm_kernel<<<grid, 256, GEMM_SMEM>>>(
            (const float*)p_xr, (const float*)p_wr, b_in,
            (float*)p_xssm, (float*)p_gate, MROWS, 2 * DD, DD, 1);
    }

    // 3) depthwise causal conv + silu
    conv_silu_kernel<<<Y_ELEMS/4/256, 256>>>(conv_w, conv_b);

    // 4) BC projection
    bc_kernel<<<MROWS/64, 256, BC_SMEM>>>(W_x, b_x);

    // 5) chunked scan
    scan1_kernel<<<BB*SEG*4, 256>>>(A_log);
    combine_kernel<<<BB*NN*DD/256, 256>>>(A_log, out + Y_ELEMS);
    scan2_kernel<<<BB*SEG*4, 256>>>(A_log, D_par);

    // 6) GEMM2: [8192,1024]@[1024,1024] -> y
    {
        dim3 grid(DD / GBN, MROWS / GBM);       // (4, 64)
        tc_gemm_kernel<<<grid, 256, GEMM_SMEM>>>(
            (const float*)p_yg, (const float*)p_wor, b_out,
            out, nullptr, MROWS, DD, DD, 0);
    }
}

// round 6
// speedup vs baseline: 1.0562x; 1.0562x over previous
#include <cuda_runtime.h>
#include <cuda_bf16.h>
#include <math.h>
#include <stdint.h>

// ---------------- problem dims ----------------
#define BB 2
#define LL 4096
#define DD 1024
#define NN 16
#define KK 4
#define SEG 32
#define TSEG 128            // LL/SEG
#define MROWS (BB*LL)       // 8192
#define Y_ELEMS (BB*LL*DD)  // 8388608

// ---------------- scratch ----------------
__device__ float g_xssm[Y_ELEMS];
__device__ float g_gate[Y_ELEMS];    // silu(gate)
__device__ float g_xconv[Y_ELEMS];
__device__ float g_yg[Y_ELEMS];      // y*silu(gate), tf32-rounded
__device__ float g_B[BB*LL*NN];
__device__ float g_C[BB*LL*NN];
__device__ float g_xr[Y_ELEMS];      // tf32-rounded x
__device__ float g_wr[2*DD*DD];      // tf32-rounded W_in
__device__ float g_wor[DD*DD];       // tf32-rounded W_out
__device__ float g_hseg[BB*SEG*NN*DD];
__device__ float g_h0[BB*SEG*NN*DD];

__device__ __forceinline__ float rtf(float f) {
    uint32_t r; asm("cvt.rna.tf32.f32 %0, %1;" : "=r"(r) : "f"(f));
    return __uint_as_float(r);
}

// ---------------- merged prep: round x/W_in/W_out + zero out-tail --------
#define X4   (Y_ELEMS/4)            // 2097152
#define W14  (2*DD*DD/4)            // 1048576
#define W24  (DD*DD/4)              // 262144
#define PREP_TOTAL (X4 + W14 + W24) // 3407872

__global__ void prep_kernel(const float* __restrict__ x,
                            const float* __restrict__ W_in,
                            const float* __restrict__ W_out,
                            float* __restrict__ tail)
{
    int i = blockIdx.x * blockDim.x + threadIdx.x;
    if (blockIdx.x == 0 && threadIdx.x < BB * NN) tail[threadIdx.x] = 0.0f;
    if (i >= PREP_TOTAL) return;
    const float4* src; float4* dst; int j;
    if (i < X4)            { src = (const float4*)x;     dst = (float4*)g_xr;  j = i; }
    else if (i < X4 + W14) { src = (const float4*)W_in;  dst = (float4*)g_wr;  j = i - X4; }
    else                   { src = (const float4*)W_out; dst = (float4*)g_wor; j = i - X4 - W14; }
    float4 v = src[j];
    v.x = rtf(v.x); v.y = rtf(v.y); v.z = rtf(v.z); v.w = rtf(v.w);
    dst[j] = v;
}

// ======= tf32 mma.sync GEMM: 128x128 block, 64x32 warp, 4-stage =========
#define GBM 128
#define GBN 128
#define GBK 16
#define ASTRIDE (GBK+4)             // 20
#define BSTRIDE (GBN+8)             // 136
#define A_STG (GBM*ASTRIDE)         // 2560 floats
#define B_STG (GBK*BSTRIDE)         // 2176 floats
#define STAGES 4
#define GEMM_SMEM (STAGES*(A_STG+B_STG)*4)   // 75776 bytes

__device__ __forceinline__ void cpasync16(void* dst, const void* src) {
    uint32_t s = (uint32_t)__cvta_generic_to_shared(dst);
    asm volatile("cp.async.cg.shared.global [%0], [%1], 16;\n" :: "r"(s), "l"(src));
}

__global__ __launch_bounds__(256)
void tc_gemm_kernel(const float* __restrict__ A, const float* __restrict__ Bm,
                    const float* __restrict__ bias,
                    float* __restrict__ C0, float* __restrict__ C1,
                    int M, int N, int K, int mode)
{
    extern __shared__ float sm[];
    float* As_ = sm;                    // [STAGES][GBM][ASTRIDE]
    float* Bs_ = sm + STAGES * A_STG;   // [STAGES][GBK][BSTRIDE]

    const int tid  = threadIdx.x;
    const int lane = tid & 31;
    const int wid  = tid >> 5;
    const int wm   = wid >> 2;          // 0..1 -> m offset wm*64
    const int wn   = wid & 3;           // 0..3 -> n offset wn*32
    const int row_c = blockIdx.y * GBM;
    const int col_c = blockIdx.x * GBN;
    const int r  = lane >> 2;           // 0..7
    const int cq = lane & 3;            // 0..3

    float acc[4][4][4];
    #pragma unroll
    for (int i = 0; i < 4; i++)
        #pragma unroll
        for (int j = 0; j < 4; j++)
            #pragma unroll
            for (int v = 0; v < 4; v++) acc[i][j][v] = 0.0f;

    const int a_row0 = tid >> 2;
    const int a_col0 = (tid & 3) * 4;
    const int b_row0 = tid >> 5;
    const int b_col0 = (tid & 31) * 4;

    auto prefetch = [&](int k0, int st) {
        float* Asb = As_ + st * A_STG;
        float* Bsb = Bs_ + st * B_STG;
        #pragma unroll
        for (int s = 0; s < 2; s++) {
            int ar = a_row0 + s * 64;
            cpasync16(&Asb[ar * ASTRIDE + a_col0],
                      A + (size_t)(row_c + ar) * K + k0 + a_col0);
            int br = b_row0 + s * 8;
            cpasync16(&Bsb[br * BSTRIDE + b_col0],
                      Bm + (size_t)(k0 + br) * N + col_c + b_col0);
        }
        asm volatile("cp.async.commit_group;");
    };

    const int nchunks = K / GBK;   // 64
    prefetch(0, 0);
    prefetch(GBK, 1);
    prefetch(2 * GBK, 2);

    for (int ch = 0; ch < nchunks; ch++) {
        if (ch + 1 >= nchunks)      asm volatile("cp.async.wait_group 0;");
        else if (ch + 2 >= nchunks) asm volatile("cp.async.wait_group 1;");
        else                        asm volatile("cp.async.wait_group 2;");
        __syncthreads();
        if (ch + 3 < nchunks) prefetch((ch + 3) * GBK, (ch + 3) & 3);

        const float* Asb = As_ + (ch & 3) * A_STG;
        const float* Bsb = Bs_ + (ch & 3) * B_STG;

        #pragma unroll
        for (int ks = 0; ks < GBK / 8; ks++) {
            uint32_t af[4][4], bf[4][2];
            #pragma unroll
            for (int mi = 0; mi < 4; mi++) {
                int row = wm * 64 + mi * 16 + r;
                int c   = ks * 8 + cq;
                af[mi][0] = __float_as_uint(Asb[row * ASTRIDE + c]);
                af[mi][1] = __float_as_uint(Asb[(row + 8) * ASTRIDE + c]);
                af[mi][2] = __float_as_uint(Asb[row * ASTRIDE + c + 4]);
                af[mi][3] = __float_as_uint(Asb[(row + 8) * ASTRIDE + c + 4]);
            }
            #pragma unroll
            for (int ni = 0; ni < 4; ni++) {
                int col = wn * 32 + ni * 8 + r;
                int kr  = ks * 8 + cq;
                bf[ni][0] = __float_as_uint(Bsb[kr * BSTRIDE + col]);
                bf[ni][1] = __float_as_uint(Bsb[(kr + 4) * BSTRIDE + col]);
            }
            #pragma unroll
            for (int mi = 0; mi < 4; mi++)
                #pragma unroll
                for (int ni = 0; ni < 4; ni++) {
                    asm volatile(
                        "mma.sync.aligned.m16n8k8.row.col.f32.tf32.tf32.f32 "
                        "{%0,%1,%2,%3}, {%4,%5,%6,%7}, {%8,%9}, {%0,%1,%2,%3};"
                        : "+f"(acc[mi][ni][0]), "+f"(acc[mi][ni][1]),
                          "+f"(acc[mi][ni][2]), "+f"(acc[mi][ni][3])
                        : "r"(af[mi][0]), "r"(af[mi][1]),
                          "r"(af[mi][2]), "r"(af[mi][3]),
                          "r"(bf[ni][0]), "r"(bf[ni][1]));
                }
        }
    }

    // epilogue: float2 stores; each 128-wide col block lies in one half
    const int halfN = N >> 1;
    const bool gate_side = (mode == 1) && (col_c >= halfN);
    float* dst = gate_side ? C1 : C0;
    const int outw = (mode == 1) ? halfN : N;
    const int colsub = gate_side ? halfN : 0;

    #pragma unroll
    for (int mi = 0; mi < 4; mi++) {
        #pragma unroll
        for (int ni = 0; ni < 4; ni++) {
            int r0   = row_c + wm * 64 + mi * 16 + r;
            int colg = col_c + wn * 32 + ni * 8 + cq * 2;
            float b0 = bias[colg], b1 = bias[colg + 1];
            #pragma unroll
            for (int hv = 0; hv < 2; hv++) {
                int rr = r0 + hv * 8;
                float2 v;
                v.x = acc[mi][ni][hv * 2 + 0] + b0;
                v.y = acc[mi][ni][hv * 2 + 1] + b1;
                if (gate_side) {
                    v.x = v.x / (1.0f + expf(-v.x));
                    v.y = v.y / (1.0f + expf(-v.y));
                }
                *(float2*)(dst + (size_t)rr * outw + colg - colsub) = v;
            }
        }
    }
}

// ---------------- depthwise causal conv (K=4) + SiLU ----------------
__global__ void conv_silu_kernel(const float* __restrict__ w,
                                 const float* __restrict__ cb)
{
    int idx = blockIdx.x * blockDim.x + threadIdx.x;
    if (idx >= Y_ELEMS / 4) return;
    int d  = idx & (DD - 1);
    int lq = (idx >> 10) & (LL / 4 - 1);
    int b  = idx >> 20;
    int l0 = lq * 4;
    const float* base = g_xssm + (size_t)b * LL * DD + d;
    float w0 = w[d * KK + 0], w1 = w[d * KK + 1],
          w2 = w[d * KK + 2], w3 = w[d * KK + 3];
    float bias = cb[d];
    float xm3 = (l0 >= 3) ? base[(size_t)(l0 - 3) * DD] : 0.0f;
    float xm2 = (l0 >= 2) ? base[(size_t)(l0 - 2) * DD] : 0.0f;
    float xm1 = (l0 >= 1) ? base[(size_t)(l0 - 1) * DD] : 0.0f;
    float x0 = base[(size_t)(l0 + 0) * DD];
    float x1 = base[(size_t)(l0 + 1) * DD];
    float x2 = base[(size_t)(l0 + 2) * DD];
    float x3 = base[(size_t)(l0 + 3) * DD];
    float* outp = g_xconv + (size_t)b * LL * DD + d;
    float v;
    v = bias + w0*xm3 + w1*xm2 + w2*xm1 + w3*x0;
    outp[(size_t)(l0+0)*DD] = v / (1.0f + expf(-v));
    v = bias + w0*xm2 + w1*xm1 + w2*x0 + w3*x1;
    outp[(size_t)(l0+1)*DD] = v / (1.0f + expf(-v));
    v = bias + w0*xm1 + w1*x0 + w2*x1 + w3*x2;
    outp[(size_t)(l0+2)*DD] = v / (1.0f + expf(-v));
    v = bias + w0*x0 + w1*x1 + w2*x2 + w3*x3;
    outp[(size_t)(l0+3)*DD] = v / (1.0f + expf(-v));
}

// ---------------- BC = x_conv @ W_x + b_x (W staged in smem once) --------
#define BC_SMEM (DD*32*4 + 8*DD*4 + 8*8*32*4)

__global__ __launch_bounds__(256)
void bc_kernel(const float* __restrict__ Wx, const float* __restrict__ bx)
{
    extern __shared__ float sm[];
    float* Wsm  = sm;
    float* rows = sm + DD * 32;
    float* psum = rows + 8 * DD;

    const int tid = threadIdx.x;
    const int c   = tid & 31;
    const int ks  = tid >> 5;
    const int r0  = blockIdx.x * 64;

    for (int i = tid; i < DD * 32 / 4; i += 256)
        ((float4*)Wsm)[i] = ((const float4*)Wx)[i];
    __syncthreads();

    for (int g = 0; g < 8; g++) {
        const float* src = g_xconv + (size_t)(r0 + g * 8) * DD;
        for (int i = tid; i < 8 * DD / 4; i += 256)
            ((float4*)rows)[i] = ((const float4*)src)[i];
        __syncthreads();

        float acc[8];
        #pragma unroll
        for (int rr = 0; rr < 8; rr++) acc[rr] = 0.0f;

        const int kbase = ks * 128;
        for (int k4 = 0; k4 < 128; k4 += 4) {
            int k = kbase + k4;
            float w0 = Wsm[(k + 0) * 32 + c];
            float w1 = Wsm[(k + 1) * 32 + c];
            float w2 = Wsm[(k + 2) * 32 + c];
            float w3 = Wsm[(k + 3) * 32 + c];
            #pragma unroll
            for (int rr = 0; rr < 8; rr++) {
                float4 xv = *(const float4*)&rows[rr * DD + k];
                acc[rr] = fmaf(xv.x, w0, fmaf(xv.y, w1,
                          fmaf(xv.z, w2, fmaf(xv.w, w3, acc[rr]))));
            }
        }
        #pragma unroll
        for (int rr = 0; rr < 8; rr++)
            psum[(rr * 8 + ks) * 32 + c] = acc[rr];
        __syncthreads();

        {
            int rr = tid >> 5;
            int c2 = tid & 31;
            float s = bx[c2];
            #pragma unroll
            for (int q = 0; q < 8; q++) s += psum[(rr * 8 + q) * 32 + c2];
            int r = r0 + g * 8 + rr;
            if (c2 < NN) g_B[r * NN + c2] = s;
            else         g_C[r * NN + (c2 - NN)] = s;
        }
        __syncthreads();
    }
}

// ---------------- scan pass 1 ----------------
__global__ __launch_bounds__(256)
void scan1_kernel(const float* __restrict__ A_log)
{
    __shared__ float Xsm[32][256];
    __shared__ __align__(16) float Bsm[32][16];

    const int tid = threadIdx.x;
    const int dt  = blockIdx.x & 3;
    const int s   = (blockIdx.x >> 2) & 31;
    const int b   = blockIdx.x >> 7;
    const int d   = dt * 256 + tid;

    float Adn[16];
    #pragma unroll
    for (int n = 0; n < 16; n++) Adn[n] = expf(-expf(A_log[d * NN + n]));

    float h[16];
    #pragma unroll
    for (int n = 0; n < 16; n++) h[n] = 0.0f;

    const float* xcp = g_xconv + (size_t)b * LL * DD + dt * 256;
    const float* Bp  = g_B + (size_t)b * LL * NN;
    const int t0 = s * TSEG;

    for (int cc = 0; cc < 4; cc++) {
        int tb = t0 + cc * 32;
        if (tid < 128)
            ((float4*)Bsm)[tid] = ((const float4*)(Bp + (size_t)tb * NN))[tid];
        #pragma unroll 8
        for (int i = 0; i < 32; i++)
            Xsm[i][tid] = xcp[(size_t)(tb + i) * DD + tid];
        __syncthreads();
        #pragma unroll 4
        for (int tl = 0; tl < 32; tl++) {
            float xc = Xsm[tl][tid];
            float4 b0 = *(const float4*)&Bsm[tl][0];
            float4 b1 = *(const float4*)&Bsm[tl][4];
            float4 b2 = *(const float4*)&Bsm[tl][8];
            float4 b3 = *(const float4*)&Bsm[tl][12];
            h[0]  = fmaf(Adn[0],  h[0],  xc * b0.x);
            h[1]  = fmaf(Adn[1],  h[1],  xc * b0.y);
            h[2]  = fmaf(Adn[2],  h[2],  xc * b0.z);
            h[3]  = fmaf(Adn[3],  h[3],  xc * b0.w);
            h[4]  = fmaf(Adn[4],  h[4],  xc * b1.x);
            h[5]  = fmaf(Adn[5],  h[5],  xc * b1.y);
            h[6]  = fmaf(Adn[6],  h[6],  xc * b1.z);
            h[7]  = fmaf(Adn[7],  h[7],  xc * b1.w);
            h[8]  = fmaf(Adn[8],  h[8],  xc * b2.x);
            h[9]  = fmaf(Adn[9],  h[9],  xc * b2.y);
            h[10] = fmaf(Adn[10], h[10], xc * b2.z);
            h[11] = fmaf(Adn[11], h[11], xc * b2.w);
            h[12] = fmaf(Adn[12], h[12], xc * b3.x);
            h[13] = fmaf(Adn[13], h[13], xc * b3.y);
            h[14] = fmaf(Adn[14], h[14], xc * b3.z);
            h[15] = fmaf(Adn[15], h[15], xc * b3.w);
        }
        __syncthreads();
    }
    #pragma unroll
    for (int n = 0; n < 16; n++)
        g_hseg[((size_t)(b * SEG + s) * NN + n) * DD + d] = h[n];
}

// ---------------- combine ----------------
__global__ __launch_bounds__(256)
void combine_kernel(const float* __restrict__ A_log, float* __restrict__ fstate)
{
    int idx = blockIdx.x * 256 + threadIdx.x;
    int d = idx & (DD - 1);
    int bn = idx >> 10;
    int n = bn & 15;
    int b = bn >> 4;

    float Adn = expf(-expf(A_log[d * NN + n]));
    float p = Adn;
    #pragma unroll
    for (int i = 0; i < 7; i++) p = p * p;

    size_t base = ((size_t)(b * SEG) * NN + n) * DD + d;
    const size_t stride = (size_t)NN * DD;
    float h = 0.0f;
    #pragma unroll 4
    for (int s = 0; s < SEG; s++) {
        g_h0[base + s * stride] = h;
        h = fmaf(p, h, g_hseg[base + s * stride]);
    }
    #pragma unroll
    for (int off = 16; off >= 1; off >>= 1)
        h += __shfl_xor_sync(0xffffffffu, h, off);
    if ((threadIdx.x & 31) == 0)
        atomicAdd(&fstate[b * NN + n], h * (1.0f / (float)DD));
}

// ---------------- scan pass 2 ----------------
__global__ __launch_bounds__(256)
void scan2_kernel(const float* __restrict__ A_log, const float* __restrict__ Dp)
{
    __shared__ float Xsm[32][256];
    __shared__ __align__(16) float Bsm[32][16];
    __shared__ __align__(16) float Csm[32][16];

    const int tid = threadIdx.x;
    const int dt  = blockIdx.x & 3;
    const int s   = (blockIdx.x >> 2) & 31;
    const int b   = blockIdx.x >> 7;
    const int d   = dt * 256 + tid;

    float Adn[16];
    #pragma unroll
    for (int n = 0; n < 16; n++) Adn[n] = expf(-expf(A_log[d * NN + n]));
    const float Dd = Dp[d];

    float h[16];
    {
        size_t base = ((size_t)(b * SEG + s) * NN) * DD + d;
        #pragma unroll
        for (int n = 0; n < 16; n++) h[n] = g_h0[base + (size_t)n * DD];
    }

    const float* xcp = g_xconv + (size_t)b * LL * DD + dt * 256;
    const float* gp  = g_gate  + (size_t)b * LL * DD + dt * 256;
    float*       yp  = g_yg    + (size_t)b * LL * DD + dt * 256;
    const float* Bp  = g_B + (size_t)b * LL * NN;
    const float* Cp  = g_C + (size_t)b * LL * NN;
    const int t0 = s * TSEG;

    for (int cc = 0; cc < 4; cc++) {
        int tb = t0 + cc * 32;
        if (tid < 128) {
            ((float4*)Bsm)[tid] = ((const float4*)(Bp + (size_t)tb * NN))[tid];
            ((float4*)Csm)[tid] = ((const float4*)(Cp + (size_t)tb * NN))[tid];
        }
        #pragma unroll 8
        for (int i = 0; i < 32; i++)
            Xsm[i][tid] = xcp[(size_t)(tb + i) * DD + tid];
        __syncthreads();
        #pragma unroll 2
        for (int tl = 0; tl < 32; tl++) {
            float xc = Xsm[tl][tid];
            float4 b0 = *(const float4*)&Bsm[tl][0];
            float4 b1 = *(const float4*)&Bsm[tl][4];
            float4 b2 = *(const float4*)&Bsm[tl][8];
            float4 b3 = *(const float4*)&Bsm[tl][12];
            h[0]  = fmaf(Adn[0],  h[0],  xc * b0.x);
            h[1]  = fmaf(Adn[1],  h[1],  xc * b0.y);
            h[2]  = fmaf(Adn[2],  h[2],  xc * b0.z);
            h[3]  = fmaf(Adn[3],  h[3],  xc * b0.w);
            h[4]  = fmaf(Adn[4],  h[4],  xc * b1.x);
            h[5]  = fmaf(Adn[5],  h[5],  xc * b1.y);
            h[6]  = fmaf(Adn[6],  h[6],  xc * b1.z);
            h[7]  = fmaf(Adn[7],  h[7],  xc * b1.w);
            h[8]  = fmaf(Adn[8],  h[8],  xc * b2.x);
            h[9]  = fmaf(Adn[9],  h[9],  xc * b2.y);
            h[10] = fmaf(Adn[10], h[10], xc * b2.z);
            h[11] = fmaf(Adn[11], h[11], xc * b2.w);
            h[12] = fmaf(Adn[12], h[12], xc * b3.x);
            h[13] = fmaf(Adn[13], h[13], xc * b3.y);
            h[14] = fmaf(Adn[14], h[14], xc * b3.z);
            h[15] = fmaf(Adn[15], h[15], xc * b3.w);
            float4 c0 = *(const float4*)&Csm[tl][0];
            float4 c1 = *(const float4*)&Csm[tl][4];
            float4 c2 = *(const float4*)&Csm[tl][8];
            float4 c3 = *(const float4*)&Csm[tl][12];
            float y0 = fmaf(c0.x, h[0],  fmaf(c0.y, h[1],
                       fmaf(c0.z, h[2],  c0.w * h[3])));
            float y1 = fmaf(c1.x, h[4],  fmaf(c1.y, h[5],
                       fmaf(c1.z, h[6],  c1.w * h[7])));
            float y2 = fmaf(c2.x, h[8],  fmaf(c2.y, h[9],
                       fmaf(c2.z, h[10], c2.w * h[11])));
            float y3 = fmaf(c3.x, h[12], fmaf(c3.y, h[13],
                       fmaf(c3.z, h[14], c3.w * h[15])));
            float y = ((y0 + y1) + (y2 + y3)) + Dd * xc;
            float gv = gp[(size_t)(tb + tl) * DD + tid];
            yp[(size_t)(tb + tl) * DD + tid] = rtf(y * gv);
        }
        __syncthreads();
    }
}

// ---------------- launcher ----------------
extern "C" void kernel_launch(void* const* d_in, const int* in_sizes, int n_in,
                              void* d_out, int out_size)
{
    const float* x      = (const float*)d_in[0];
    const float* W_in   = (const float*)d_in[1];
    const float* b_in   = (const float*)d_in[2];
    const float* conv_w = (const float*)d_in[3];
    const float* conv_b = (const float*)d_in[4];
    const float* W_x    = (const float*)d_in[5];
    const float* b_x    = (const float*)d_in[6];
    const float* A_log  = (const float*)d_in[7];
    const float* D_par  = (const float*)d_in[8];
    const float* W_out  = (const float*)d_in[9];
    const float* b_out  = (const float*)d_in[10];
    float* out = (float*)d_out;

    static int attr_done = 0;
    if (!attr_done) {
        cudaFuncSetAttribute(tc_gemm_kernel,
            cudaFuncAttributeMaxDynamicSharedMemorySize, GEMM_SMEM);
        cudaFuncSetAttribute(bc_kernel,
            cudaFuncAttributeMaxDynamicSharedMemorySize, BC_SMEM);
        attr_done = 1;
    }

    void *p_xssm, *p_gate, *p_yg, *p_xr, *p_wr, *p_wor;
    cudaGetSymbolAddress(&p_xssm, g_xssm);
    cudaGetSymbolAddress(&p_gate, g_gate);
    cudaGetSymbolAddress(&p_yg,   g_yg);
    cudaGetSymbolAddress(&p_xr,   g_xr);
    cudaGetSymbolAddress(&p_wr,   g_wr);
    cudaGetSymbolAddress(&p_wor,  g_wor);

    // 1) prep: round x/W_in/W_out to tf32 + zero final_state tail
    prep_kernel<<<(PREP_TOTAL + 255) / 256, 256>>>(x, W_in, W_out, out + Y_ELEMS);

    // 2) GEMM1: [8192,1024]@[1024,2048] -> (x_ssm raw, silu(gate))
    {
        dim3 grid(2 * DD / GBN, MROWS / GBM);   // (16, 64)
        tc_gemm_kernel<<<grid, 256, GEMM_SMEM>>>(
            (const float*)p_xr, (const float*)p_wr, b_in,
            (float*)p_xssm, (float*)p_gate, MROWS, 2 * DD, DD, 1);
    }

    // 3) depthwise causal conv + silu
    conv_silu_kernel<<<Y_ELEMS/4/256, 256>>>(conv_w, conv_b);

    // 4) BC projection
    bc_kernel<<<MROWS/64, 256, BC_SMEM>>>(W_x, b_x);

    // 5) chunked scan
    scan1_kernel<<<BB*SEG*4, 256>>>(A_log);
    combine_kernel<<<BB*NN*DD/256, 256>>>(A_log, out + Y_ELEMS);
    scan2_kernel<<<BB*SEG*4, 256>>>(A_log, D_par);

    // 6) GEMM2: [8192,1024]@[1024,1024] -> y
    {
        dim3 grid(DD / GBN, MROWS / GBM);       // (8, 64)
        tc_gemm_kernel<<<grid, 256, GEMM_SMEM>>>(
            (const float*)p_yg, (const float*)p_wor, b_out,
            out, nullptr, MROWS, DD, DD, 0);
    }
}

// round 7
// speedup vs baseline: 1.1960x; 1.1323x over previous
#include <cuda_runtime.h>
#include <cuda_bf16.h>
#include <math.h>
#include <stdint.h>

// ---------------- problem dims ----------------
#define BB 2
#define LL 4096
#define DD 1024
#define NN 16
#define KK 4
#define SEG 64
#define TSEG 64             // LL/SEG
#define MROWS (BB*LL)       // 8192
#define Y_ELEMS (BB*LL*DD)  // 8388608

// ---------------- scratch ----------------
__device__ float g_xssm[Y_ELEMS];
__device__ float g_gate[Y_ELEMS];    // silu(gate)
__device__ float g_xconv[Y_ELEMS];
__device__ float g_yg[Y_ELEMS];      // y*silu(gate), tf32-rounded
__device__ float g_B[BB*LL*NN];
__device__ float g_C[BB*LL*NN];
__device__ float g_xr[Y_ELEMS];      // tf32-rounded x
__device__ float g_wr[2*DD*DD];      // tf32-rounded W_in
__device__ float g_wor[DD*DD];       // tf32-rounded W_out
__device__ float g_wxr[DD*2*NN];     // tf32-rounded W_x
__device__ float g_hseg[BB*SEG*NN*DD];
__device__ float g_h0[BB*SEG*NN*DD];

__device__ __forceinline__ float rtf(float f) {
    uint32_t r; asm("cvt.rna.tf32.f32 %0, %1;" : "=r"(r) : "f"(f));
    return __uint_as_float(r);
}

// ---------------- merged prep: round x/W_in/W_out/W_x + zero out-tail ----
#define X4   (Y_ELEMS/4)
#define W14  (2*DD*DD/4)
#define W24  (DD*DD/4)
#define WX4  (DD*2*NN/4)
#define PREP_TOTAL (X4 + W14 + W24 + WX4)

__global__ void prep_kernel(const float* __restrict__ x,
                            const float* __restrict__ W_in,
                            const float* __restrict__ W_out,
                            const float* __restrict__ W_x,
                            float* __restrict__ tail)
{
    int i = blockIdx.x * blockDim.x + threadIdx.x;
    if (blockIdx.x == 0 && threadIdx.x < BB * NN) tail[threadIdx.x] = 0.0f;
    if (i >= PREP_TOTAL) return;
    const float4* src; float4* dst; int j;
    if (i < X4)                  { src = (const float4*)x;     dst = (float4*)g_xr;  j = i; }
    else if (i < X4 + W14)       { src = (const float4*)W_in;  dst = (float4*)g_wr;  j = i - X4; }
    else if (i < X4 + W14 + W24) { src = (const float4*)W_out; dst = (float4*)g_wor; j = i - X4 - W14; }
    else                         { src = (const float4*)W_x;   dst = (float4*)g_wxr; j = i - X4 - W14 - W24; }
    float4 v = src[j];
    v.x = rtf(v.x); v.y = rtf(v.y); v.z = rtf(v.z); v.w = rtf(v.w);
    dst[j] = v;
}

// ======= tf32 mma.sync GEMM: 128x128 block, 64x32 warp, 3-stage (R3) ====
#define GBM 128
#define GBN 128
#define GBK 16
#define ASTRIDE (GBK+4)             // 20
#define BSTRIDE (GBN+8)             // 136
#define A_STG (GBM*ASTRIDE)         // 2560 floats
#define B_STG (GBK*BSTRIDE)         // 2176 floats
#define STAGES 3
#define GEMM_SMEM (STAGES*(A_STG+B_STG)*4)   // 56832 bytes

__device__ __forceinline__ void cpasync16(void* dst, const void* src) {
    uint32_t s = (uint32_t)__cvta_generic_to_shared(dst);
    asm volatile("cp.async.cg.shared.global [%0], [%1], 16;\n" :: "r"(s), "l"(src));
}

__global__ __launch_bounds__(256)
void tc_gemm_kernel(const float* __restrict__ A, const float* __restrict__ Bm,
                    const float* __restrict__ bias,
                    float* __restrict__ C0, float* __restrict__ C1,
                    int M, int N, int K, int mode)
{
    extern __shared__ float sm[];
    float* As_ = sm;
    float* Bs_ = sm + STAGES * A_STG;

    const int tid  = threadIdx.x;
    const int lane = tid & 31;
    const int wid  = tid >> 5;
    const int wm   = wid >> 2;
    const int wn   = wid & 3;
    const int row_c = blockIdx.y * GBM;
    const int col_c = blockIdx.x * GBN;
    const int r  = lane >> 2;
    const int cq = lane & 3;

    float acc[4][4][4];
    #pragma unroll
    for (int i = 0; i < 4; i++)
        #pragma unroll
        for (int j = 0; j < 4; j++)
            #pragma unroll
            for (int v = 0; v < 4; v++) acc[i][j][v] = 0.0f;

    const int a_row0 = tid >> 2;
    const int a_col0 = (tid & 3) * 4;
    const int b_row0 = tid >> 5;
    const int b_col0 = (tid & 31) * 4;

    auto prefetch = [&](int k0, int st) {
        float* Asb = As_ + st * A_STG;
        float* Bsb = Bs_ + st * B_STG;
        #pragma unroll
        for (int s = 0; s < 2; s++) {
            int ar = a_row0 + s * 64;
            cpasync16(&Asb[ar * ASTRIDE + a_col0],
                      A + (size_t)(row_c + ar) * K + k0 + a_col0);
            int br = b_row0 + s * 8;
            cpasync16(&Bsb[br * BSTRIDE + b_col0],
                      Bm + (size_t)(k0 + br) * N + col_c + b_col0);
        }
        asm volatile("cp.async.commit_group;");
    };

    const int nchunks = K / GBK;   // 64
    prefetch(0, 0);
    prefetch(GBK, 1);

    for (int ch = 0; ch < nchunks; ch++) {
        if (ch >= nchunks - 2) asm volatile("cp.async.wait_group 0;");
        else                   asm volatile("cp.async.wait_group 1;");
        __syncthreads();
        if (ch + 2 < nchunks) prefetch((ch + 2) * GBK, (ch + 2) % STAGES);

        const float* Asb = As_ + (ch % STAGES) * A_STG;
        const float* Bsb = Bs_ + (ch % STAGES) * B_STG;

        #pragma unroll
        for (int ks = 0; ks < GBK / 8; ks++) {
            uint32_t af[4][4], bf[4][2];
            #pragma unroll
            for (int mi = 0; mi < 4; mi++) {
                int row = wm * 64 + mi * 16 + r;
                int c   = ks * 8 + cq;
                af[mi][0] = __float_as_uint(Asb[row * ASTRIDE + c]);
                af[mi][1] = __float_as_uint(Asb[(row + 8) * ASTRIDE + c]);
                af[mi][2] = __float_as_uint(Asb[row * ASTRIDE + c + 4]);
                af[mi][3] = __float_as_uint(Asb[(row + 8) * ASTRIDE + c + 4]);
            }
            #pragma unroll
            for (int ni = 0; ni < 4; ni++) {
                int col = wn * 32 + ni * 8 + r;
                int kr  = ks * 8 + cq;
                bf[ni][0] = __float_as_uint(Bsb[kr * BSTRIDE + col]);
                bf[ni][1] = __float_as_uint(Bsb[(kr + 4) * BSTRIDE + col]);
            }
            #pragma unroll
            for (int mi = 0; mi < 4; mi++)
                #pragma unroll
                for (int ni = 0; ni < 4; ni++) {
                    asm volatile(
                        "mma.sync.aligned.m16n8k8.row.col.f32.tf32.tf32.f32 "
                        "{%0,%1,%2,%3}, {%4,%5,%6,%7}, {%8,%9}, {%0,%1,%2,%3};"
                        : "+f"(acc[mi][ni][0]), "+f"(acc[mi][ni][1]),
                          "+f"(acc[mi][ni][2]), "+f"(acc[mi][ni][3])
                        : "r"(af[mi][0]), "r"(af[mi][1]),
                          "r"(af[mi][2]), "r"(af[mi][3]),
                          "r"(bf[ni][0]), "r"(bf[ni][1]));
                }
        }
        __syncthreads();
    }

    const int halfN = N >> 1;
    const bool gate_side = (mode == 1) && (col_c >= halfN);
    float* dst = gate_side ? C1 : C0;
    const int outw = (mode == 1) ? halfN : N;
    const int colsub = gate_side ? halfN : 0;

    #pragma unroll
    for (int mi = 0; mi < 4; mi++) {
        #pragma unroll
        for (int ni = 0; ni < 4; ni++) {
            int r0   = row_c + wm * 64 + mi * 16 + r;
            int colg = col_c + wn * 32 + ni * 8 + cq * 2;
            float b0 = bias[colg], b1 = bias[colg + 1];
            #pragma unroll
            for (int hv = 0; hv < 2; hv++) {
                int rr = r0 + hv * 8;
                float2 v;
                v.x = acc[mi][ni][hv * 2 + 0] + b0;
                v.y = acc[mi][ni][hv * 2 + 1] + b1;
                if (gate_side) {
                    v.x = v.x / (1.0f + expf(-v.x));
                    v.y = v.y / (1.0f + expf(-v.y));
                }
                *(float2*)(dst + (size_t)rr * outw + colg - colsub) = v;
            }
        }
    }
}

// ---------------- depthwise causal conv (K=4) + SiLU, float4 over d -----
__global__ void conv_silu_kernel(const float* __restrict__ w,
                                 const float* __restrict__ cb)
{
    int idx = blockIdx.x * blockDim.x + threadIdx.x;   // Y_ELEMS/16 threads
    if (idx >= Y_ELEMS / 16) return;
    int d0 = (idx & 255) * 4;
    int l0 = ((idx >> 8) & 1023) * 4;
    int b  = idx >> 18;
    const float* base = g_xssm + (size_t)b * LL * DD;

    float4 xv[7];
    #pragma unroll
    for (int j = 0; j < 7; j++) {
        int l = l0 - 3 + j;
        xv[j] = (l >= 0) ? *(const float4*)(base + (size_t)l * DD + d0)
                         : make_float4(0.f, 0.f, 0.f, 0.f);
    }
    float4 wr0 = *(const float4*)(w + (d0 + 0) * KK);
    float4 wr1 = *(const float4*)(w + (d0 + 1) * KK);
    float4 wr2 = *(const float4*)(w + (d0 + 2) * KK);
    float4 wr3 = *(const float4*)(w + (d0 + 3) * KK);
    float4 cbv = *(const float4*)(cb + d0);

    float* outp = g_xconv + (size_t)b * LL * DD;
    #pragma unroll
    for (int l = 0; l < 4; l++) {
        float4 v;
        v.x = cbv.x + wr0.x*xv[l].x + wr0.y*xv[l+1].x + wr0.z*xv[l+2].x + wr0.w*xv[l+3].x;
        v.y = cbv.y + wr1.x*xv[l].y + wr1.y*xv[l+1].y + wr1.z*xv[l+2].y + wr1.w*xv[l+3].y;
        v.z = cbv.z + wr2.x*xv[l].z + wr2.y*xv[l+1].z + wr2.z*xv[l+2].z + wr2.w*xv[l+3].z;
        v.w = cbv.w + wr3.x*xv[l].w + wr3.y*xv[l+1].w + wr3.z*xv[l+2].w + wr3.w*xv[l+3].w;
        v.x = v.x / (1.0f + expf(-v.x));
        v.y = v.y / (1.0f + expf(-v.y));
        v.z = v.z / (1.0f + expf(-v.z));
        v.w = v.w / (1.0f + expf(-v.w));
        *(float4*)(outp + (size_t)(l0 + l) * DD + d0) = v;
    }
}

// ---------------- BC via tensor cores: [8192,1024]@[1024,32] ------------
// block: 128 threads (4 warps), 64 rows; warp = 16 rows x 32 cols.
__global__ __launch_bounds__(128)
void bc_mma_kernel(const float* __restrict__ Wxr, const float* __restrict__ bx)
{
    __shared__ float As[3][64][36];
    __shared__ float Ws[3][32][40];

    const int tid  = threadIdx.x;
    const int lane = tid & 31;
    const int wid  = tid >> 5;        // 0..3
    const int r    = lane >> 2;
    const int cq   = lane & 3;
    const int r0   = blockIdx.x * 64;

    float acc[4][4];
    #pragma unroll
    for (int i = 0; i < 4; i++)
        #pragma unroll
        for (int v = 0; v < 4; v++) acc[i][v] = 0.0f;

    auto prefetch = [&](int ch, int st) {
        const int k0 = ch * 32;
        #pragma unroll
        for (int p = 0; p < 4; p++) {       // A: 64x32 = 512 float4
            int i2 = tid + p * 128;
            int row = i2 >> 3, sub = i2 & 7;
            cpasync16(&As[st][row][sub * 4],
                      g_xconv + (size_t)(r0 + row) * DD + k0 + sub * 4);
        }
        #pragma unroll
        for (int p = 0; p < 2; p++) {       // W: 32x32 = 256 float4
            int i2 = tid + p * 128;
            int row = i2 >> 3, sub = i2 & 7;
            cpasync16(&Ws[st][row][sub * 4],
                      Wxr + (size_t)(k0 + row) * 32 + sub * 4);
        }
        asm volatile("cp.async.commit_group;");
    };

    const int nch = DD / 32;   // 32
    prefetch(0, 0);
    prefetch(1, 1);

    for (int ch = 0; ch < nch; ch++) {
        if (ch >= nch - 2) asm volatile("cp.async.wait_group 0;");
        else               asm volatile("cp.async.wait_group 1;");
        __syncthreads();
        if (ch + 2 < nch) prefetch(ch + 2, (ch + 2) % 3);

        const int buf = ch % 3;
        #pragma unroll
        for (int ks = 0; ks < 4; ks++) {
            uint32_t af[4], bf[4][2];
            int row = wid * 16 + r;
            int c   = ks * 8 + cq;
            af[0] = __float_as_uint(As[buf][row][c]);
            af[1] = __float_as_uint(As[buf][row + 8][c]);
            af[2] = __float_as_uint(As[buf][row][c + 4]);
            af[3] = __float_as_uint(As[buf][row + 8][c + 4]);
            #pragma unroll
            for (int ni = 0; ni < 4; ni++) {
                bf[ni][0] = __float_as_uint(Ws[buf][ks * 8 + cq][ni * 8 + r]);
                bf[ni][1] = __float_as_uint(Ws[buf][ks * 8 + cq + 4][ni * 8 + r]);
            }
            #pragma unroll
            for (int ni = 0; ni < 4; ni++) {
                asm volatile(
                    "mma.sync.aligned.m16n8k8.row.col.f32.tf32.tf32.f32 "
                    "{%0,%1,%2,%3}, {%4,%5,%6,%7}, {%8,%9}, {%0,%1,%2,%3};"
                    : "+f"(acc[ni][0]), "+f"(acc[ni][1]),
                      "+f"(acc[ni][2]), "+f"(acc[ni][3])
                    : "r"(af[0]), "r"(af[1]), "r"(af[2]), "r"(af[3]),
                      "r"(bf[ni][0]), "r"(bf[ni][1]));
            }
        }
        __syncthreads();
    }

    #pragma unroll
    for (int ni = 0; ni < 4; ni++) {
        #pragma unroll
        for (int v = 0; v < 4; v++) {
            int row = r0 + wid * 16 + r + (v >> 1) * 8;
            int col = ni * 8 + cq * 2 + (v & 1);
            float val = acc[ni][v] + bx[col];
            if (col < NN) g_B[row * NN + col] = val;
            else          g_C[row * NN + (col - NN)] = val;
        }
    }
}

// ---------------- scan pass 1 ----------------
__global__ __launch_bounds__(256)
void scan1_kernel(const float* __restrict__ A_log)
{
    __shared__ float Xsm[32][256];
    __shared__ __align__(16) float Bsm[32][16];

    const int tid = threadIdx.x;
    const int dt  = blockIdx.x & 3;
    const int s   = (blockIdx.x >> 2) & (SEG - 1);
    const int b   = blockIdx.x >> 8;
    const int d   = dt * 256 + tid;

    float Adn[16];
    #pragma unroll
    for (int n = 0; n < 16; n++) Adn[n] = expf(-expf(A_log[d * NN + n]));

    float h[16];
    #pragma unroll
    for (int n = 0; n < 16; n++) h[n] = 0.0f;

    const float* xcp = g_xconv + (size_t)b * LL * DD + dt * 256;
    const float* Bp  = g_B + (size_t)b * LL * NN;
    const int t0 = s * TSEG;

    for (int cc = 0; cc < TSEG / 32; cc++) {
        int tb = t0 + cc * 32;
        if (tid < 128)
            ((float4*)Bsm)[tid] = ((const float4*)(Bp + (size_t)tb * NN))[tid];
        #pragma unroll 8
        for (int i = 0; i < 32; i++)
            Xsm[i][tid] = xcp[(size_t)(tb + i) * DD + tid];
        __syncthreads();
        #pragma unroll 4
        for (int tl = 0; tl < 32; tl++) {
            float xc = Xsm[tl][tid];
            float4 b0 = *(const float4*)&Bsm[tl][0];
            float4 b1 = *(const float4*)&Bsm[tl][4];
            float4 b2 = *(const float4*)&Bsm[tl][8];
            float4 b3 = *(const float4*)&Bsm[tl][12];
            h[0]  = fmaf(Adn[0],  h[0],  xc * b0.x);
            h[1]  = fmaf(Adn[1],  h[1],  xc * b0.y);
            h[2]  = fmaf(Adn[2],  h[2],  xc * b0.z);
            h[3]  = fmaf(Adn[3],  h[3],  xc * b0.w);
            h[4]  = fmaf(Adn[4],  h[4],  xc * b1.x);
            h[5]  = fmaf(Adn[5],  h[5],  xc * b1.y);
            h[6]  = fmaf(Adn[6],  h[6],  xc * b1.z);
            h[7]  = fmaf(Adn[7],  h[7],  xc * b1.w);
            h[8]  = fmaf(Adn[8],  h[8],  xc * b2.x);
            h[9]  = fmaf(Adn[9],  h[9],  xc * b2.y);
            h[10] = fmaf(Adn[10], h[10], xc * b2.z);
            h[11] = fmaf(Adn[11], h[11], xc * b2.w);
            h[12] = fmaf(Adn[12], h[12], xc * b3.x);
            h[13] = fmaf(Adn[13], h[13], xc * b3.y);
            h[14] = fmaf(Adn[14], h[14], xc * b3.z);
            h[15] = fmaf(Adn[15], h[15], xc * b3.w);
        }
        __syncthreads();
    }
    #pragma unroll
    for (int n = 0; n < 16; n++)
        g_hseg[((size_t)(b * SEG + s) * NN + n) * DD + d] = h[n];
}

// ---------------- combine ----------------
__global__ __launch_bounds__(256)
void combine_kernel(const float* __restrict__ A_log, float* __restrict__ fstate)
{
    int idx = blockIdx.x * 256 + threadIdx.x;
    int d = idx & (DD - 1);
    int bn = idx >> 10;
    int n = bn & 15;
    int b = bn >> 4;

    float Adn = expf(-expf(A_log[d * NN + n]));
    float p = Adn;
    #pragma unroll
    for (int i = 0; i < 6; i++) p = p * p;   // Adn^64 (TSEG=64)

    size_t base = ((size_t)(b * SEG) * NN + n) * DD + d;
    const size_t stride = (size_t)NN * DD;
    float h = 0.0f;
    #pragma unroll 4
    for (int s = 0; s < SEG; s++) {
        g_h0[base + s * stride] = h;
        h = fmaf(p, h, g_hseg[base + s * stride]);
    }
    #pragma unroll
    for (int off = 16; off >= 1; off >>= 1)
        h += __shfl_xor_sync(0xffffffffu, h, off);
    if ((threadIdx.x & 31) == 0)
        atomicAdd(&fstate[b * NN + n], h * (1.0f / (float)DD));
}

// ---------------- scan pass 2 ----------------
__global__ __launch_bounds__(256)
void scan2_kernel(const float* __restrict__ A_log, const float* __restrict__ Dp)
{
    __shared__ float Xsm[32][256];
    __shared__ __align__(16) float Bsm[32][16];
    __shared__ __align__(16) float Csm[32][16];

    const int tid = threadIdx.x;
    const int dt  = blockIdx.x & 3;
    const int s   = (blockIdx.x >> 2) & (SEG - 1);
    const int b   = blockIdx.x >> 8;
    const int d   = dt * 256 + tid;

    float Adn[16];
    #pragma unroll
    for (int n = 0; n < 16; n++) Adn[n] = expf(-expf(A_log[d * NN + n]));
    const float Dd = Dp[d];

    float h[16];
    {
        size_t base = ((size_t)(b * SEG + s) * NN) * DD + d;
        #pragma unroll
        for (int n = 0; n < 16; n++) h[n] = g_h0[base + (size_t)n * DD];
    }

    const float* xcp = g_xconv + (size_t)b * LL * DD + dt * 256;
    const float* gp  = g_gate  + (size_t)b * LL * DD + dt * 256;
    float*       yp  = g_yg    + (size_t)b * LL * DD + dt * 256;
    const float* Bp  = g_B + (size_t)b * LL * NN;
    const float* Cp  = g_C + (size_t)b * LL * NN;
    const int t0 = s * TSEG;

    for (int cc = 0; cc < TSEG / 32; cc++) {
        int tb = t0 + cc * 32;
        if (tid < 128) {
            ((float4*)Bsm)[tid] = ((const float4*)(Bp + (size_t)tb * NN))[tid];
            ((float4*)Csm)[tid] = ((const float4*)(Cp + (size_t)tb * NN))[tid];
        }
        #pragma unroll 8
        for (int i = 0; i < 32; i++)
            Xsm[i][tid] = xcp[(size_t)(tb + i) * DD + tid];
        __syncthreads();
        #pragma unroll 2
        for (int tl = 0; tl < 32; tl++) {
            float xc = Xsm[tl][tid];
            float4 b0 = *(const float4*)&Bsm[tl][0];
            float4 b1 = *(const float4*)&Bsm[tl][4];
            float4 b2 = *(const float4*)&Bsm[tl][8];
            float4 b3 = *(const float4*)&Bsm[tl][12];
            h[0]  = fmaf(Adn[0],  h[0],  xc * b0.x);
            h[1]  = fmaf(Adn[1],  h[1],  xc * b0.y);
            h[2]  = fmaf(Adn[2],  h[2],  xc * b0.z);
            h[3]  = fmaf(Adn[3],  h[3],  xc * b0.w);
            h[4]  = fmaf(Adn[4],  h[4],  xc * b1.x);
            h[5]  = fmaf(Adn[5],  h[5],  xc * b1.y);
            h[6]  = fmaf(Adn[6],  h[6],  xc * b1.z);
            h[7]  = fmaf(Adn[7],  h[7],  xc * b1.w);
            h[8]  = fmaf(Adn[8],  h[8],  xc * b2.x);
            h[9]  = fmaf(Adn[9],  h[9],  xc * b2.y);
            h[10] = fmaf(Adn[10], h[10], xc * b2.z);
            h[11] = fmaf(Adn[11], h[11], xc * b2.w);
            h[12] = fmaf(Adn[12], h[12], xc * b3.x);
            h[13] = fmaf(Adn[13], h[13], xc * b3.y);
            h[14] = fmaf(Adn[14], h[14], xc * b3.z);
            h[15] = fmaf(Adn[15], h[15], xc * b3.w);
            float4 c0 = *(const float4*)&Csm[tl][0];
            float4 c1 = *(const float4*)&Csm[tl][4];
            float4 c2 = *(const float4*)&Csm[tl][8];
            float4 c3 = *(const float4*)&Csm[tl][12];
            float y0 = fmaf(c0.x, h[0],  fmaf(c0.y, h[1],
                       fmaf(c0.z, h[2],  c0.w * h[3])));
            float y1 = fmaf(c1.x, h[4],  fmaf(c1.y, h[5],
                       fmaf(c1.z, h[6],  c1.w * h[7])));
            float y2 = fmaf(c2.x, h[8],  fmaf(c2.y, h[9],
                       fmaf(c2.z, h[10], c2.w * h[11])));
            float y3 = fmaf(c3.x, h[12], fmaf(c3.y, h[13],
                       fmaf(c3.z, h[14], c3.w * h[15])));
            float y = ((y0 + y1) + (y2 + y3)) + Dd * xc;
            float gv = gp[(size_t)(tb + tl) * DD + tid];
            yp[(size_t)(tb + tl) * DD + tid] = rtf(y * gv);
        }
        __syncthreads();
    }
}

// ---------------- launcher ----------------
extern "C" void kernel_launch(void* const* d_in, const int* in_sizes, int n_in,
                              void* d_out, int out_size)
{
    const float* x      = (const float*)d_in[0];
    const float* W_in   = (const float*)d_in[1];
    const float* b_in   = (const float*)d_in[2];
    const float* conv_w = (const float*)d_in[3];
    const float* conv_b = (const float*)d_in[4];
    const float* W_x    = (const float*)d_in[5];
    const float* b_x    = (const float*)d_in[6];
    const float* A_log  = (const float*)d_in[7];
    const float* D_par  = (const float*)d_in[8];
    const float* W_out  = (const float*)d_in[9];
    const float* b_out  = (const float*)d_in[10];
    float* out = (float*)d_out;

    static int attr_done = 0;
    if (!attr_done) {
        cudaFuncSetAttribute(tc_gemm_kernel,
            cudaFuncAttributeMaxDynamicSharedMemorySize, GEMM_SMEM);
        attr_done = 1;
    }

    void *p_xssm, *p_gate, *p_yg, *p_xr, *p_wr, *p_wor, *p_wxr;
    cudaGetSymbolAddress(&p_xssm, g_xssm);
    cudaGetSymbolAddress(&p_gate, g_gate);
    cudaGetSymbolAddress(&p_yg,   g_yg);
    cudaGetSymbolAddress(&p_xr,   g_xr);
    cudaGetSymbolAddress(&p_wr,   g_wr);
    cudaGetSymbolAddress(&p_wor,  g_wor);
    cudaGetSymbolAddress(&p_wxr,  g_wxr);

    // 1) prep: round x/W_in/W_out/W_x + zero final_state tail
    prep_kernel<<<(PREP_TOTAL + 255) / 256, 256>>>(x, W_in, W_out, W_x, out + Y_ELEMS);

    // 2) GEMM1: [8192,1024]@[1024,2048] -> (x_ssm raw, silu(gate))
    {
        dim3 grid(2 * DD / GBN, MROWS / GBM);
        tc_gemm_kernel<<<grid, 256, GEMM_SMEM>>>(
            (const float*)p_xr, (const float*)p_wr, b_in,
            (float*)p_xssm, (float*)p_gate, MROWS, 2 * DD, DD, 1);
    }

    // 3) depthwise causal conv + silu (float4 over d)
    conv_silu_kernel<<<Y_ELEMS/16/256, 256>>>(conv_w, conv_b);

    // 4) BC projection (tensor cores)
    bc_mma_kernel<<<MROWS/64, 128>>>((const float*)p_wxr, b_x);

    // 5) chunked scan (SEG=64)
    scan1_kernel<<<BB*SEG*4, 256>>>(A_log);
    combine_kernel<<<BB*NN*DD/256, 256>>>(A_log, out + Y_ELEMS);
    scan2_kernel<<<BB*SEG*4, 256>>>(A_log, D_par);

    // 6) GEMM2: [8192,1024]@[1024,1024] -> y
    {
        dim3 grid(DD / GBN, MROWS / GBM);
        tc_gemm_kernel<<<grid, 256, GEMM_SMEM>>>(
            (const float*)p_yg, (const float*)p_wor, b_out,
            out, nullptr, MROWS, DD, DD, 0);
    }
}

// round 9
// speedup vs baseline: 1.8425x; 1.5406x over previous
#include <cuda_runtime.h>
#include <cuda_fp16.h>
#include <math.h>
#include <stdint.h>

// ---------------- problem dims ----------------
#define BB 2
#define LL 4096
#define DD 1024
#define NN 16
#define KK 4
#define SEG 64
#define TSEG 64
#define MROWS (BB*LL)       // 8192
#define Y_ELEMS (BB*LL*DD)  // 8388608

// ---------------- scratch ----------------
__device__ float g_xssm[Y_ELEMS];
__device__ float g_gate[Y_ELEMS];          // silu(gate)
__device__ float g_xconv[Y_ELEMS];
__device__ __align__(16) __half g_xh[Y_ELEMS];     // fp16 x
__device__ __align__(16) __half g_ygh[Y_ELEMS];    // fp16 y*silu(gate)
__device__ __align__(16) uint32_t g_wp1[(DD/2)*(2*DD)];  // W_in pair-packed
__device__ __align__(16) uint32_t g_wp2[(DD/2)*DD];      // W_out pair-packed
__device__ float g_wxr[DD*2*NN];           // tf32-rounded W_x
__device__ float g_B[BB*LL*NN];
__device__ float g_C[BB*LL*NN];
__device__ float g_hseg[BB*SEG*NN*DD];
__device__ float g_h0[BB*SEG*NN*DD];

__device__ __forceinline__ float rtf(float f) {
    uint32_t r; asm("cvt.rna.tf32.f32 %0, %1;" : "=r"(r) : "f"(f));
    return __uint_as_float(r);
}
__device__ __forceinline__ uint32_t h2u(__half2 h) {
    union { __half2 h; uint32_t u; } cvt; cvt.h = h; return cvt.u;
}

// ---------------- merged prep ----------------
#define X4   (Y_ELEMS/4)                 // 2097152 (float4 -> 2x half2)
#define WP1N ((DD/2)*(2*DD))             // 1048576
#define WP2N ((DD/2)*DD)                 // 524288
#define WXR4 (DD*2*NN/4)                 // 8192
#define PREP_TOTAL (X4 + WP1N + WP2N + WXR4)

__global__ void prep_kernel(const float* __restrict__ x,
                            const float* __restrict__ W_in,
                            const float* __restrict__ W_out,
                            const float* __restrict__ W_x,
                            float* __restrict__ tail)
{
    int i = blockIdx.x * blockDim.x + threadIdx.x;
    if (blockIdx.x == 0 && threadIdx.x < BB * NN) tail[threadIdx.x] = 0.0f;
    if (i >= PREP_TOTAL) return;
    if (i < X4) {
        float4 v = ((const float4*)x)[i];
        uint2 o;
        o.x = h2u(__floats2half2_rn(v.x, v.y));
        o.y = h2u(__floats2half2_rn(v.z, v.w));
        ((uint2*)g_xh)[i] = o;
    } else if (i < X4 + WP1N) {
        int j = i - X4;
        int k2 = j >> 11, n = j & 2047;
        float lo = W_in[(size_t)(2 * k2) * 2048 + n];
        float hi = W_in[(size_t)(2 * k2 + 1) * 2048 + n];
        g_wp1[j] = h2u(__floats2half2_rn(lo, hi));
    } else if (i < X4 + WP1N + WP2N) {
        int j = i - X4 - WP1N;
        int k2 = j >> 10, n = j & 1023;
        float lo = W_out[(size_t)(2 * k2) * 1024 + n];
        float hi = W_out[(size_t)(2 * k2 + 1) * 1024 + n];
        g_wp2[j] = h2u(__floats2half2_rn(lo, hi));
    } else {
        int j = i - X4 - WP1N - WP2N;
        float4 v = ((const float4*)W_x)[j];
        v.x = rtf(v.x); v.y = rtf(v.y); v.z = rtf(v.z); v.w = rtf(v.w);
        ((float4*)g_wxr)[j] = v;
    }
}

// ======= fp16 mma.sync GEMM (m16n8k16): 128x128 block, 64x32 warp ======
#define GBM 128
#define GBN 128
#define GBK 32                       // halves per chunk
#define AWSTRIDE 20                  // uint32 per A row (32 halves + 8 pad)
#define BWSTRIDE 136                 // uint32 per B pair-row (128 + 8 pad)
#define A_STGW (GBM*AWSTRIDE)        // 2560 uint32
#define B_STGW (16*BWSTRIDE)         // 2176 uint32
#define STAGES 3
#define GEMM_SMEM (STAGES*(A_STGW+B_STGW)*4)   // 56832 bytes

__device__ __forceinline__ void cpasync16(void* dst, const void* src) {
    uint32_t s = (uint32_t)__cvta_generic_to_shared(dst);
    asm volatile("cp.async.cg.shared.global [%0], [%1], 16;\n" :: "r"(s), "l"(src));
}

__global__ __launch_bounds__(256)
void hgemm_kernel(const __half* __restrict__ A, const uint32_t* __restrict__ Bp,
                  const float* __restrict__ bias,
                  float* __restrict__ C0, float* __restrict__ C1,
                  int M, int N, int K, int mode)
{
    extern __shared__ uint32_t smw[];
    uint32_t* As_ = smw;                       // [STAGES][128][20]
    uint32_t* Bs_ = smw + STAGES * A_STGW;     // [STAGES][16][136]

    const int tid  = threadIdx.x;
    const int lane = tid & 31;
    const int wid  = tid >> 5;
    const int wm   = wid >> 2;
    const int wn   = wid & 3;
    const int row_c = blockIdx.y * GBM;
    const int col_c = blockIdx.x * GBN;
    const int r  = lane >> 2;
    const int cq = lane & 3;

    float acc[4][4][4];
    #pragma unroll
    for (int i = 0; i < 4; i++)
        #pragma unroll
        for (int j = 0; j < 4; j++)
            #pragma unroll
            for (int v = 0; v < 4; v++) acc[i][j][v] = 0.0f;

    auto prefetch = [&](int k0, int st) {
        uint32_t* Asb = As_ + st * A_STGW;
        uint32_t* Bsb = Bs_ + st * B_STGW;
        #pragma unroll
        for (int s = 0; s < 2; s++) {
            int i2 = tid + s * 256;
            int arow = i2 >> 2, asub = i2 & 3;       // 4 x 16B per row
            cpasync16(&Asb[arow * AWSTRIDE + asub * 4],
                      A + (size_t)(row_c + arow) * K + k0 + asub * 8);
            int brow = i2 >> 5, bsub = (i2 & 31) * 4;  // 16 rows x 32 x 16B
            cpasync16(&Bsb[brow * BWSTRIDE + bsub],
                      Bp + (size_t)(k0 / 2 + brow) * N + col_c + bsub);
        }
        asm volatile("cp.async.commit_group;");
    };

    const int nchunks = K / GBK;   // 32
    prefetch(0, 0);
    prefetch(GBK, 1);

    for (int ch = 0; ch < nchunks; ch++) {
        if (ch >= nchunks - 2) asm volatile("cp.async.wait_group 0;");
        else                   asm volatile("cp.async.wait_group 1;");
        __syncthreads();
        if (ch + 2 < nchunks) prefetch((ch + 2) * GBK, (ch + 2) % STAGES);

        const uint32_t* Asb = As_ + (ch % STAGES) * A_STGW;
        const uint32_t* Bsb = Bs_ + (ch % STAGES) * B_STGW;

        #pragma unroll
        for (int ks = 0; ks < 2; ks++) {           // two k16 steps
            uint32_t af[4][4], bf[4][2];
            #pragma unroll
            for (int mi = 0; mi < 4; mi++) {
                int row = wm * 64 + mi * 16 + r;
                int w0  = ks * 8 + cq;
                af[mi][0] = Asb[row * AWSTRIDE + w0];
                af[mi][1] = Asb[(row + 8) * AWSTRIDE + w0];
                af[mi][2] = Asb[row * AWSTRIDE + w0 + 4];
                af[mi][3] = Asb[(row + 8) * AWSTRIDE + w0 + 4];
            }
            #pragma unroll
            for (int ni = 0; ni < 4; ni++) {
                int col = wn * 32 + ni * 8 + r;
                bf[ni][0] = Bsb[(ks * 8 + cq) * BWSTRIDE + col];
                bf[ni][1] = Bsb[(ks * 8 + cq + 4) * BWSTRIDE + col];
            }
            #pragma unroll
            for (int mi = 0; mi < 4; mi++)
                #pragma unroll
                for (int ni = 0; ni < 4; ni++) {
                    asm volatile(
                        "mma.sync.aligned.m16n8k16.row.col.f32.f16.f16.f32 "
                        "{%0,%1,%2,%3}, {%4,%5,%6,%7}, {%8,%9}, {%0,%1,%2,%3};"
                        : "+f"(acc[mi][ni][0]), "+f"(acc[mi][ni][1]),
                          "+f"(acc[mi][ni][2]), "+f"(acc[mi][ni][3])
                        : "r"(af[mi][0]), "r"(af[mi][1]),
                          "r"(af[mi][2]), "r"(af[mi][3]),
                          "r"(bf[ni][0]), "r"(bf[ni][1]));
                }
        }
        __syncthreads();
    }

    const int halfN = N >> 1;
    const bool gate_side = (mode == 1) && (col_c >= halfN);
    float* dst = gate_side ? C1 : C0;
    const int outw = (mode == 1) ? halfN : N;
    const int colsub = gate_side ? halfN : 0;

    #pragma unroll
    for (int mi = 0; mi < 4; mi++) {
        #pragma unroll
        for (int ni = 0; ni < 4; ni++) {
            int r0   = row_c + wm * 64 + mi * 16 + r;
            int colg = col_c + wn * 32 + ni * 8 + cq * 2;
            float b0 = bias[colg], b1 = bias[colg + 1];
            #pragma unroll
            for (int hv = 0; hv < 2; hv++) {
                int rr = r0 + hv * 8;
                float2 v;
                v.x = acc[mi][ni][hv * 2 + 0] + b0;
                v.y = acc[mi][ni][hv * 2 + 1] + b1;
                if (gate_side) {
                    v.x = v.x / (1.0f + expf(-v.x));
                    v.y = v.y / (1.0f + expf(-v.y));
                }
                *(float2*)(dst + (size_t)rr * outw + colg - colsub) = v;
            }
        }
    }
}

// ---------------- depthwise causal conv (K=4) + SiLU, float4 over d -----
__global__ void conv_silu_kernel(const float* __restrict__ w,
                                 const float* __restrict__ cb)
{
    int idx = blockIdx.x * blockDim.x + threadIdx.x;
    if (idx >= Y_ELEMS / 16) return;
    int d0 = (idx & 255) * 4;
    int l0 = ((idx >> 8) & 1023) * 4;
    int b  = idx >> 18;
    const float* base = g_xssm + (size_t)b * LL * DD;

    float4 xv[7];
    #pragma unroll
    for (int j = 0; j < 7; j++) {
        int l = l0 - 3 + j;
        xv[j] = (l >= 0) ? *(const float4*)(base + (size_t)l * DD + d0)
                         : make_float4(0.f, 0.f, 0.f, 0.f);
    }
    float4 wr0 = *(const float4*)(w + (d0 + 0) * KK);
    float4 wr1 = *(const float4*)(w + (d0 + 1) * KK);
    float4 wr2 = *(const float4*)(w + (d0 + 2) * KK);
    float4 wr3 = *(const float4*)(w + (d0 + 3) * KK);
    float4 cbv = *(const float4*)(cb + d0);

    float* outp = g_xconv + (size_t)b * LL * DD;
    #pragma unroll
    for (int l = 0; l < 4; l++) {
        float4 v;
        v.x = cbv.x + wr0.x*xv[l].x + wr0.y*xv[l+1].x + wr0.z*xv[l+2].x + wr0.w*xv[l+3].x;
        v.y = cbv.y + wr1.x*xv[l].y + wr1.y*xv[l+1].y + wr1.z*xv[l+2].y + wr1.w*xv[l+3].y;
        v.z = cbv.z + wr2.x*xv[l].z + wr2.y*xv[l+1].z + wr2.z*xv[l+2].z + wr2.w*xv[l+3].z;
        v.w = cbv.w + wr3.x*xv[l].w + wr3.y*xv[l+1].w + wr3.z*xv[l+2].w + wr3.w*xv[l+3].w;
        v.x = v.x / (1.0f + expf(-v.x));
        v.y = v.y / (1.0f + expf(-v.y));
        v.z = v.z / (1.0f + expf(-v.z));
        v.w = v.w / (1.0f + expf(-v.w));
        *(float4*)(outp + (size_t)(l0 + l) * DD + d0) = v;
    }
}

// ---------------- BC via tensor cores (tf32, RNA-rounded A) -------------
__global__ __launch_bounds__(128)
void bc_mma_kernel(const float* __restrict__ Wxr, const float* __restrict__ bx)
{
    __shared__ float As[3][64][36];
    __shared__ float Ws[3][32][40];

    const int tid  = threadIdx.x;
    const int lane = tid & 31;
    const int wid  = tid >> 5;
    const int r    = lane >> 2;
    const int cq   = lane & 3;
    const int r0   = blockIdx.x * 64;

    float acc[4][4];
    #pragma unroll
    for (int i = 0; i < 4; i++)
        #pragma unroll
        for (int v = 0; v < 4; v++) acc[i][v] = 0.0f;

    auto prefetch = [&](int ch, int st) {
        const int k0 = ch * 32;
        #pragma unroll
        for (int p = 0; p < 4; p++) {
            int i2 = tid + p * 128;
            int row = i2 >> 3, sub = i2 & 7;
            cpasync16(&As[st][row][sub * 4],
                      g_xconv + (size_t)(r0 + row) * DD + k0 + sub * 4);
        }
        #pragma unroll
        for (int p = 0; p < 2; p++) {
            int i2 = tid + p * 128;
            int row = i2 >> 3, sub = i2 & 7;
            cpasync16(&Ws[st][row][sub * 4],
                      Wxr + (size_t)(k0 + row) * 32 + sub * 4);
        }
        asm volatile("cp.async.commit_group;");
    };

    const int nch = DD / 32;
    prefetch(0, 0);
    prefetch(1, 1);

    for (int ch = 0; ch < nch; ch++) {
        if (ch >= nch - 2) asm volatile("cp.async.wait_group 0;");
        else               asm volatile("cp.async.wait_group 1;");
        __syncthreads();
        if (ch + 2 < nch) prefetch(ch + 2, (ch + 2) % 3);

        const int buf = ch % 3;
        #pragma unroll
        for (int ks = 0; ks < 4; ks++) {
            uint32_t af[4], bf[4][2];
            int row = wid * 16 + r;
            int c   = ks * 8 + cq;
            af[0] = __float_as_uint(rtf(As[buf][row][c]));
            af[1] = __float_as_uint(rtf(As[buf][row + 8][c]));
            af[2] = __float_as_uint(rtf(As[buf][row][c + 4]));
            af[3] = __float_as_uint(rtf(As[buf][row + 8][c + 4]));
            #pragma unroll
            for (int ni = 0; ni < 4; ni++) {
                bf[ni][0] = __float_as_uint(Ws[buf][ks * 8 + cq][ni * 8 + r]);
                bf[ni][1] = __float_as_uint(Ws[buf][ks * 8 + cq + 4][ni * 8 + r]);
            }
            #pragma unroll
            for (int ni = 0; ni < 4; ni++) {
                asm volatile(
                    "mma.sync.aligned.m16n8k8.row.col.f32.tf32.tf32.f32 "
                    "{%0,%1,%2,%3}, {%4,%5,%6,%7}, {%8,%9}, {%0,%1,%2,%3};"
                    : "+f"(acc[ni][0]), "+f"(acc[ni][1]),
                      "+f"(acc[ni][2]), "+f"(acc[ni][3])
                    : "r"(af[0]), "r"(af[1]), "r"(af[2]), "r"(af[3]),
                      "r"(bf[ni][0]), "r"(bf[ni][1]));
            }
        }
        __syncthreads();
    }

    #pragma unroll
    for (int ni = 0; ni < 4; ni++) {
        #pragma unroll
        for (int v = 0; v < 4; v++) {
            int row = r0 + wid * 16 + r + (v >> 1) * 8;
            int col = ni * 8 + cq * 2 + (v & 1);
            float val = acc[ni][v] + bx[col];
            if (col < NN) g_B[row * NN + col] = val;
            else          g_C[row * NN + (col - NN)] = val;
        }
    }
}

// ---------------- scan pass 1 ----------------
__global__ __launch_bounds__(256)
void scan1_kernel(const float* __restrict__ A_log)
{
    __shared__ float Xsm[32][256];
    __shared__ __align__(16) float Bsm[32][16];

    const int tid = threadIdx.x;
    const int dt  = blockIdx.x & 3;
    const int s   = (blockIdx.x >> 2) & (SEG - 1);
    const int b   = blockIdx.x >> 8;
    const int d   = dt * 256 + tid;

    float Adn[16];
    #pragma unroll
    for (int n = 0; n < 16; n++) Adn[n] = expf(-expf(A_log[d * NN + n]));

    float h[16];
    #pragma unroll
    for (int n = 0; n < 16; n++) h[n] = 0.0f;

    const float* xcp = g_xconv + (size_t)b * LL * DD + dt * 256;
    const float* Bp  = g_B + (size_t)b * LL * NN;
    const int t0 = s * TSEG;

    for (int cc = 0; cc < TSEG / 32; cc++) {
        int tb = t0 + cc * 32;
        if (tid < 128)
            ((float4*)Bsm)[tid] = ((const float4*)(Bp + (size_t)tb * NN))[tid];
        #pragma unroll 8
        for (int i = 0; i < 32; i++)
            Xsm[i][tid] = xcp[(size_t)(tb + i) * DD + tid];
        __syncthreads();
        #pragma unroll 4
        for (int tl = 0; tl < 32; tl++) {
            float xc = Xsm[tl][tid];
            float4 b0 = *(const float4*)&Bsm[tl][0];
            float4 b1 = *(const float4*)&Bsm[tl][4];
            float4 b2 = *(const float4*)&Bsm[tl][8];
            float4 b3 = *(const float4*)&Bsm[tl][12];
            h[0]  = fmaf(Adn[0],  h[0],  xc * b0.x);
            h[1]  = fmaf(Adn[1],  h[1],  xc * b0.y);
            h[2]  = fmaf(Adn[2],  h[2],  xc * b0.z);
            h[3]  = fmaf(Adn[3],  h[3],  xc * b0.w);
            h[4]  = fmaf(Adn[4],  h[4],  xc * b1.x);
            h[5]  = fmaf(Adn[5],  h[5],  xc * b1.y);
            h[6]  = fmaf(Adn[6],  h[6],  xc * b1.z);
            h[7]  = fmaf(Adn[7],  h[7],  xc * b1.w);
            h[8]  = fmaf(Adn[8],  h[8],  xc * b2.x);
            h[9]  = fmaf(Adn[9],  h[9],  xc * b2.y);
            h[10] = fmaf(Adn[10], h[10], xc * b2.z);
            h[11] = fmaf(Adn[11], h[11], xc * b2.w);
            h[12] = fmaf(Adn[12], h[12], xc * b3.x);
            h[13] = fmaf(Adn[13], h[13], xc * b3.y);
            h[14] = fmaf(Adn[14], h[14], xc * b3.z);
            h[15] = fmaf(Adn[15], h[15], xc * b3.w);
        }
        __syncthreads();
    }
    #pragma unroll
    for (int n = 0; n < 16; n++)
        g_hseg[((size_t)(b * SEG + s) * NN + n) * DD + d] = h[n];
}

// ---------------- combine ----------------
__global__ __launch_bounds__(256)
void combine_kernel(const float* __restrict__ A_log, float* __restrict__ fstate)
{
    int idx = blockIdx.x * 256 + threadIdx.x;
    int d = idx & (DD - 1);
    int bn = idx >> 10;
    int n = bn & 15;
    int b = bn >> 4;

    float Adn = expf(-expf(A_log[d * NN + n]));
    float p = Adn;
    #pragma unroll
    for (int i = 0; i < 6; i++) p = p * p;   // Adn^64

    size_t base = ((size_t)(b * SEG) * NN + n) * DD + d;
    const size_t stride = (size_t)NN * DD;
    float h = 0.0f;
    #pragma unroll 4
    for (int s = 0; s < SEG; s++) {
        g_h0[base + s * stride] = h;
        h = fmaf(p, h, g_hseg[base + s * stride]);
    }
    #pragma unroll
    for (int off = 16; off >= 1; off >>= 1)
        h += __shfl_xor_sync(0xffffffffu, h, off);
    if ((threadIdx.x & 31) == 0)
        atomicAdd(&fstate[b * NN + n], h * (1.0f / (float)DD));
}

// ---------------- scan pass 2 (emit yg as fp16) ----------------
__global__ __launch_bounds__(256)
void scan2_kernel(const float* __restrict__ A_log, const float* __restrict__ Dp)
{
    __shared__ float Xsm[32][256];
    __shared__ __align__(16) float Bsm[32][16];
    __shared__ __align__(16) float Csm[32][16];

    const int tid = threadIdx.x;
    const int dt  = blockIdx.x & 3;
    const int s   = (blockIdx.x >> 2) & (SEG - 1);
    const int b   = blockIdx.x >> 8;
    const int d   = dt * 256 + tid;

    float Adn[16];
    #pragma unroll
    for (int n = 0; n < 16; n++) Adn[n] = expf(-expf(A_log[d * NN + n]));
    const float Dd = Dp[d];

    float h[16];
    {
        size_t base = ((size_t)(b * SEG + s) * NN) * DD + d;
        #pragma unroll
        for (int n = 0; n < 16; n++) h[n] = g_h0[base + (size_t)n * DD];
    }

    const float* xcp = g_xconv + (size_t)b * LL * DD + dt * 256;
    const float* gp  = g_gate  + (size_t)b * LL * DD + dt * 256;
    __half*      yp  = g_ygh   + (size_t)b * LL * DD + dt * 256;
    const float* Bp  = g_B + (size_t)b * LL * NN;
    const float* Cp  = g_C + (size_t)b * LL * NN;
    const int t0 = s * TSEG;

    for (int cc = 0; cc < TSEG / 32; cc++) {
        int tb = t0 + cc * 32;
        if (tid < 128) {
            ((float4*)Bsm)[tid] = ((const float4*)(Bp + (size_t)tb * NN))[tid];
            ((float4*)Csm)[tid] = ((const float4*)(Cp + (size_t)tb * NN))[tid];
        }
        #pragma unroll 8
        for (int i = 0; i < 32; i++)
            Xsm[i][tid] = xcp[(size_t)(tb + i) * DD + tid];
        __syncthreads();
        #pragma unroll 2
        for (int tl = 0; tl < 32; tl++) {
            float xc = Xsm[tl][tid];
            float4 b0 = *(const float4*)&Bsm[tl][0];
            float4 b1 = *(const float4*)&Bsm[tl][4];
            float4 b2 = *(const float4*)&Bsm[tl][8];
            float4 b3 = *(const float4*)&Bsm[tl][12];
            h[0]  = fmaf(Adn[0],  h[0],  xc * b0.x);
            h[1]  = fmaf(Adn[1],  h[1],  xc * b0.y);
            h[2]  = fmaf(Adn[2],  h[2],  xc * b0.z);
            h[3]  = fmaf(Adn[3],  h[3],  xc * b0.w);
            h[4]  = fmaf(Adn[4],  h[4],  xc * b1.x);
            h[5]  = fmaf(Adn[5],  h[5],  xc * b1.y);
            h[6]  = fmaf(Adn[6],  h[6],  xc * b1.z);
            h[7]  = fmaf(Adn[7],  h[7],  xc * b1.w);
            h[8]  = fmaf(Adn[8],  h[8],  xc * b2.x);
            h[9]  = fmaf(Adn[9],  h[9],  xc * b2.y);
            h[10] = fmaf(Adn[10], h[10], xc * b2.z);
            h[11] = fmaf(Adn[11], h[11], xc * b2.w);
            h[12] = fmaf(Adn[12], h[12], xc * b3.x);
            h[13] = fmaf(Adn[13], h[13], xc * b3.y);
            h[14] = fmaf(Adn[14], h[14], xc * b3.z);
            h[15] = fmaf(Adn[15], h[15], xc * b3.w);
            float4 c0 = *(const float4*)&Csm[tl][0];
            float4 c1 = *(const float4*)&Csm[tl][4];
            float4 c2 = *(const float4*)&Csm[tl][8];
            float4 c3 = *(const float4*)&Csm[tl][12];
            float y0 = fmaf(c0.x, h[0],  fmaf(c0.y, h[1],
                       fmaf(c0.z, h[2],  c0.w * h[3])));
            float y1 = fmaf(c1.x, h[4],  fmaf(c1.y, h[5],
                       fmaf(c1.z, h[6],  c1.w * h[7])));
            float y2 = fmaf(c2.x, h[8],  fmaf(c2.y, h[9],
                       fmaf(c2.z, h[10], c2.w * h[11])));
            float y3 = fmaf(c3.x, h[12], fmaf(c3.y, h[13],
                       fmaf(c3.z, h[14], c3.w * h[15])));
            float y = ((y0 + y1) + (y2 + y3)) + Dd * xc;
            float gv = gp[(size_t)(tb + tl) * DD + tid];
            yp[(size_t)(tb + tl) * DD + tid] = __float2half_rn(y * gv);
        }
        __syncthreads();
    }
}

// ---------------- launcher ----------------
extern "C" void kernel_launch(void* const* d_in, const int* in_sizes, int n_in,
                              void* d_out, int out_size)
{
    const float* x      = (const float*)d_in[0];
    const float* W_in   = (const float*)d_in[1];
    const float* b_in   = (const float*)d_in[2];
    const float* conv_w = (const float*)d_in[3];
    const float* conv_b = (const float*)d_in[4];
    const float* W_x    = (const float*)d_in[5];
    const float* b_x    = (const float*)d_in[6];
    const float* A_log  = (const float*)d_in[7];
    const float* D_par  = (const float*)d_in[8];
    const float* W_out  = (const float*)d_in[9];
    const float* b_out  = (const float*)d_in[10];
    float* out = (float*)d_out;

    static int attr_done = 0;
    if (!attr_done) {
        cudaFuncSetAttribute(hgemm_kernel,
            cudaFuncAttributeMaxDynamicSharedMemorySize, GEMM_SMEM);
        attr_done = 1;
    }

    void *p_xssm, *p_gate, *p_xh, *p_ygh, *p_wp1, *p_wp2, *p_wxr;
    cudaGetSymbolAddress(&p_xssm, g_xssm);
    cudaGetSymbolAddress(&p_gate, g_gate);
    cudaGetSymbolAddress(&p_xh,   g_xh);
    cudaGetSymbolAddress(&p_ygh,  g_ygh);
    cudaGetSymbolAddress(&p_wp1,  g_wp1);
    cudaGetSymbolAddress(&p_wp2,  g_wp2);
    cudaGetSymbolAddress(&p_wxr,  g_wxr);

    // 1) prep
    prep_kernel<<<(PREP_TOTAL + 255) / 256, 256>>>(x, W_in, W_out, W_x, out + Y_ELEMS);

    // 2) GEMM1 (fp16): [8192,1024]@[1024,2048] -> (x_ssm raw, silu(gate))
    {
        dim3 grid(2 * DD / GBN, MROWS / GBM);
        hgemm_kernel<<<grid, 256, GEMM_SMEM>>>(
            (const __half*)p_xh, (const uint32_t*)p_wp1, b_in,
            (float*)p_xssm, (float*)p_gate, MROWS, 2 * DD, DD, 1);
    }

    // 3) depthwise causal conv + silu
    conv_silu_kernel<<<Y_ELEMS/16/256, 256>>>(conv_w, conv_b);

    // 4) BC projection (tf32 tensor cores, RNA-rounded)
    bc_mma_kernel<<<MROWS/64, 128>>>((const float*)p_wxr, b_x);

    // 5) chunked scan
    scan1_kernel<<<BB*SEG*4, 256>>>(A_log);
    combine_kernel<<<BB*NN*DD/256, 256>>>(A_log, out + Y_ELEMS);
    scan2_kernel<<<BB*SEG*4, 256>>>(A_log, D_par);

    // 6) GEMM2 (fp16): [8192,1024]@[1024,1024] -> y
    {
        dim3 grid(DD / GBN, MROWS / GBM);
        hgemm_kernel<<<grid, 256, GEMM_SMEM>>>(
            (const __half*)p_ygh, (const uint32_t*)p_wp2, b_out,
            out, nullptr, MROWS, DD, DD, 0);
    }
}